// round 12
// baseline (speedup 1.0000x reference)
#include <cuda_runtime.h>
#include <math.h>
#include <stdint.h>

#define BB 8
#define NN 128
#define CC 128
#define C2 256
#define HH 4
#define DKK 32
#define BN_SCALE 0.9999950000374997f

__device__ float g_ep[BB*NN*NN];
__device__ float g_Q[BB*NN*CC];
__device__ float g_K[BB*NN*CC];
__device__ float g_vp1[BB*NN*CC];
__device__ float g_vp2[BB*NN*CC];
__device__ uint4 g_w1P[3 * 4096];   // bf16 fragment-packed w1 per set
__device__ uint4 g_w2P[3 * 4096];   // bf16 fragment-packed w2 per set

__device__ __forceinline__ float lrelu(float x) { return x > 0.f ? x : 0.01f * x; }
__device__ __forceinline__ uint32_t pack_bf16(float lo, float hi) {
    uint32_t r; asm("cvt.rn.bf16x2.f32 %0, %1, %2;" : "=r"(r) : "f"(hi), "f"(lo)); return r;
}

__device__ __forceinline__ void mma_bf16(float* c, const uint4& a, uint32_t b0, uint32_t b1) {
    asm volatile(
        "mma.sync.aligned.m16n8k16.row.col.f32.bf16.bf16.f32 "
        "{%0,%1,%2,%3}, {%4,%5,%6,%7}, {%8,%9}, {%0,%1,%2,%3};"
        : "+f"(c[0]), "+f"(c[1]), "+f"(c[2]), "+f"(c[3])
        : "r"(a.x), "r"(a.y), "r"(a.z), "r"(a.w), "r"(b0), "r"(b1));
}

// ---------------- weight prep (all 3 sets in one launch) ---------------------
__global__ void prep_weights_all(const float* __restrict__ pw1, const float* __restrict__ pw2,
                                 const float* __restrict__ psw1, const float* __restrict__ psw2,
                                 uint4* __restrict__ w1P, uint4* __restrict__ w2P)
{
    const int set = blockIdx.y;
    const float* w1 = (set == 0) ? pw1 : psw1 + (set - 1) * CC * C2;
    const float* w2 = (set == 0) ? pw2 : psw2 + (set - 1) * C2 * CC;
    uint4* o1 = w1P + set * 4096;
    uint4* o2 = w2P + set * 4096;
    int idx = blockIdx.x * 256 + threadIdx.x;   // 0..4095
    {
        int lane = idx & 31, kt = (idx >> 5) & 7, np = (idx >> 8) & 1, ch = idx >> 9;
        int o0 = ch * 32 + np * 16 + (lane >> 2);
        int k0 = kt * 16 + (lane & 3) * 2;
        uint4 v;
        v.x = pack_bf16(w1[k0 * C2 + o0],       w1[(k0 + 1) * C2 + o0]);
        v.y = pack_bf16(w1[(k0 + 8) * C2 + o0], w1[(k0 + 9) * C2 + o0]);
        v.z = pack_bf16(w1[k0 * C2 + o0 + 8],       w1[(k0 + 1) * C2 + o0 + 8]);
        v.w = pack_bf16(w1[(k0 + 8) * C2 + o0 + 8], w1[(k0 + 9) * C2 + o0 + 8]);
        o1[idx] = v;
    }
    {
        int lane = idx & 31, ktl = (idx >> 5) & 7, ntp = (idx >> 8) & 7, kh = idx >> 11;
        int o0 = ntp * 16 + (lane >> 2);
        int k0 = (kh * 8 + ktl) * 16 + (lane & 3) * 2;
        uint4 v;
        v.x = pack_bf16(w2[k0 * CC + o0],       w2[(k0 + 1) * CC + o0]);
        v.y = pack_bf16(w2[(k0 + 8) * CC + o0], w2[(k0 + 9) * CC + o0]);
        v.z = pack_bf16(w2[k0 * CC + o0 + 8],       w2[(k0 + 1) * CC + o0 + 8]);
        v.w = pack_bf16(w2[(k0 + 8) * CC + o0 + 8], w2[(k0 + 9) * CC + o0 + 8]);
        o2[idx] = v;
    }
}

// ---------------- psim via bf16 mma.sync (unchanged) -------------------------
#define MS_SIM  0
#define MS_H1   32768
#define MS_VPI  98304
#define MS_W3S  98816
#define MS_EPL  99328
#define MS_EROW 99840
#define MS_RED  100352
#define MS_L3   100864
#define SMEM_PS 101888

__global__ void __launch_bounds__(256, 2)
psim_mma(const float* __restrict__ vp,
         const float* __restrict__ ep_in,
         float* __restrict__ ep_out,
         const uint4* __restrict__ w1P,
         const uint4* __restrict__ w2P,
         const float* __restrict__ w3,
         const float* __restrict__ b3,
         int kval)
{
    extern __shared__ char smem[];
    float* s_vpi  = (float*)(smem + MS_VPI);
    float* s_w3   = (float*)(smem + MS_W3S);
    float* s_epl  = (float*)(smem + MS_EPL);
    float* s_erow = (float*)(smem + MS_EROW);
    float* s_red  = (float*)(smem + MS_RED);
    float* s_l3   = (float*)(smem + MS_L3);
    const int i = blockIdx.x, b = blockIdx.y;
    const int tid = threadIdx.x, w = tid >> 5, lane = tid & 31;
    const int wm = w & 3, wn = w >> 2;
    const int row = b * NN + i;

    if (tid < 128) {
        s_vpi[tid] = vp[row * CC + tid];
        s_w3[tid]  = w3[tid];
        float v = ep_in[row * NN + tid];
        s_epl[tid] = (tid == i) ? 0.f : v;
    }
    __syncthreads();

    for (int q = tid; q < 4096; q += 256) {
        int j = q >> 5, c0 = (q & 31) << 2;
        const float4 vj = *(const float4*)(vp + (b * NN + j) * CC + c0);
        const float4 vi = *(const float4*)(s_vpi + c0);
        float d0 = vi.x - vj.x, d1 = vi.y - vj.y, d2 = vi.z - vj.z, d3 = vi.w - vj.w;
        uint32_t p01 = pack_bf16(d0 * d0, d1 * d1);
        uint32_t p23 = pack_bf16(d2 * d2, d3 * d3);
        int kt = c0 >> 4, mt = j >> 4;
        uint32_t addr = (uint32_t)(((kt * 8 + mt) * 32 + (j & 7) * 4 + ((c0 & 7) >> 1)) * 16
                       + (((j >> 3) & 1) + (((c0 & 15) >> 3) << 1)) * 4);
        *(uint32_t*)(smem + MS_SIM + addr)      = p01;
        *(uint32_t*)(smem + MS_SIM + addr + 16) = p23;
    }
    __syncthreads();

    uint4 Areg[8][2];
    #pragma unroll
    for (int kt = 0; kt < 8; kt++)
        #pragma unroll
        for (int m = 0; m < 2; m++)
            Areg[kt][m] = *(const uint4*)(smem + MS_SIM + ((kt * 8 + wm * 2 + m) * 32 + lane) * 16);
    uint4 pf0 = __ldg(w1P + tid), pf1 = __ldg(w1P + 256 + tid);
    __syncthreads();

    *(uint4*)(smem + MS_SIM + tid * 16) = pf0;
    *(uint4*)(smem + MS_SIM + (256 + tid) * 16) = pf1;
    pf0 = __ldg(w1P + 512 + tid);
    pf1 = __ldg(w1P + 512 + 256 + tid);
    __syncthreads();

    for (int ch = 0; ch < 8; ch++) {
        const char* buf = smem + MS_SIM + (ch & 1) * 8192;
        float acc[2][2][4];
        #pragma unroll
        for (int m = 0; m < 2; m++)
            #pragma unroll
            for (int n = 0; n < 2; n++)
                #pragma unroll
                for (int t = 0; t < 4; t++) acc[m][n][t] = 0.f;
        #pragma unroll
        for (int kt = 0; kt < 8; kt++) {
            uint4 W = *(const uint4*)(buf + ((wn * 8 + kt) * 32 + lane) * 16);
            mma_bf16(acc[0][0], Areg[kt][0], W.x, W.y);
            mma_bf16(acc[0][1], Areg[kt][0], W.z, W.w);
            mma_bf16(acc[1][0], Areg[kt][1], W.x, W.y);
            mma_bf16(acc[1][1], Areg[kt][1], W.z, W.w);
        }
        if (ch < 7) {
            char* nb = smem + MS_SIM + ((ch + 1) & 1) * 8192;
            *(uint4*)(nb + tid * 16) = pf0;
            *(uint4*)(nb + (256 + tid) * 16) = pf1;
            if (ch < 6) {
                pf0 = __ldg(w1P + (ch + 2) * 512 + tid);
                pf1 = __ldg(w1P + (ch + 2) * 512 + 256 + tid);
            }
        }
        #pragma unroll
        for (int m = 0; m < 2; m++)
            #pragma unroll
            for (int ntl = 0; ntl < 2; ntl++) {
                uint2 st;
                st.x = pack_bf16(lrelu(acc[m][ntl][0] * BN_SCALE), lrelu(acc[m][ntl][1] * BN_SCALE));
                st.y = pack_bf16(lrelu(acc[m][ntl][2] * BN_SCALE), lrelu(acc[m][ntl][3] * BN_SCALE));
                uint32_t addr = (uint32_t)((((ch * 2 + wn) * 8 + wm * 2 + m) * 32 + lane) * 16 + ntl * 8);
                *(uint2*)(smem + MS_H1 + addr) = st;
            }
        __syncthreads();
    }

    float acc2[2][8][4];
    #pragma unroll
    for (int m = 0; m < 2; m++)
        #pragma unroll
        for (int n = 0; n < 8; n++)
            #pragma unroll
            for (int t = 0; t < 4; t++) acc2[m][n][t] = 0.f;

    for (int kh = 0; kh < 2; kh++) {
        uint4 pf2[4];
        #pragma unroll
        for (int t = 0; t < 4; t++) pf2[t] = __ldg(w2P + kh * 2048 + tid + t * 256);
        __syncthreads();
        #pragma unroll
        for (int t = 0; t < 4; t++)
            *(uint4*)(smem + MS_SIM + (tid + t * 256) * 16) = pf2[t];
        #pragma unroll
        for (int t = 0; t < 4; t++) pf2[t] = __ldg(w2P + kh * 2048 + 1024 + tid + t * 256);
        #pragma unroll
        for (int t = 0; t < 4; t++)
            *(uint4*)(smem + MS_SIM + (1024 + tid + t * 256) * 16) = pf2[t];
        __syncthreads();
        #pragma unroll 2
        for (int ktl = 0; ktl < 8; ktl++) {
            int kt2 = kh * 8 + ktl;
            uint4 A0 = *(const uint4*)(smem + MS_H1 + ((kt2 * 8 + wm * 2) * 32 + lane) * 16);
            uint4 A1 = *(const uint4*)(smem + MS_H1 + ((kt2 * 8 + wm * 2 + 1) * 32 + lane) * 16);
            #pragma unroll
            for (int pp = 0; pp < 4; pp++) {
                uint4 W = *(const uint4*)(smem + MS_SIM + (((wn * 4 + pp) * 8 + ktl) * 32 + lane) * 16);
                int q = pp * 2;
                mma_bf16(acc2[0][q],     A0, W.x, W.y);
                mma_bf16(acc2[0][q + 1], A0, W.z, W.w);
                mma_bf16(acc2[1][q],     A1, W.x, W.y);
                mma_bf16(acc2[1][q + 1], A1, W.z, W.w);
            }
        }
    }

    const float b3v = b3[0];
    float pr[4] = {0.f, 0.f, 0.f, 0.f};
    #pragma unroll
    for (int m = 0; m < 2; m++)
        #pragma unroll
        for (int q = 0; q < 8; q++) {
            int o = wn * 64 + q * 8 + (lane & 3) * 2;
            float wa = s_w3[o], wb = s_w3[o + 1];
            pr[m * 2]     += lrelu(acc2[m][q][0] * BN_SCALE) * wa + lrelu(acc2[m][q][1] * BN_SCALE) * wb;
            pr[m * 2 + 1] += lrelu(acc2[m][q][2] * BN_SCALE) * wa + lrelu(acc2[m][q][3] * BN_SCALE) * wb;
        }
    #pragma unroll
    for (int t = 0; t < 4; t++) {
        pr[t] += __shfl_xor_sync(0xffffffffu, pr[t], 1);
        pr[t] += __shfl_xor_sync(0xffffffffu, pr[t], 2);
    }
    if ((lane & 3) == 0) {
        int g = lane >> 2;
        s_l3[wn * 128 + wm * 32 + g]      = pr[0];
        s_l3[wn * 128 + wm * 32 + g + 8]  = pr[1];
        s_l3[wn * 128 + wm * 32 + g + 16] = pr[2];
        s_l3[wn * 128 + wm * 32 + g + 24] = pr[3];
    }
    __syncthreads();
    if (tid < 128) {
        float e = s_l3[tid] + s_l3[128 + tid];
        s_erow[tid] = 1.0f / (1.0f + expf(-(e + b3v)));
    }
    __syncthreads();

    if (tid < 128) s_red[tid] = s_epl[tid];
    __syncthreads();
    for (int st = 64; st > 0; st >>= 1) { if (tid < st) s_red[tid] += s_red[tid + st]; __syncthreads(); }
    const float epsum = s_red[0];
    __syncthreads();

    if (tid < 128) s_erow[tid] *= s_epl[tid];
    __syncthreads();

    if (kval > 0 && kval < NN) {
        int cnt = 0;
        if (tid < 128) {
            float mine = s_erow[tid];
            for (int jj = 0; jj < NN; jj++) {
                float v = s_erow[jj];
                cnt += (v > mine) || (v == mine && jj < tid);
            }
        }
        __syncthreads();
        if (tid < 128 && cnt >= kval) s_erow[tid] = 0.f;
        __syncthreads();
    }

    if (tid < 128) s_red[tid] = fabsf(s_erow[tid]);
    __syncthreads();
    for (int st = 64; st > 0; st >>= 1) { if (tid < st) s_red[tid] += s_red[tid + st]; __syncthreads(); }
    const float l1 = s_red[0];
    __syncthreads();

    const float scale = epsum / fmaxf(l1, 1e-12f);
    if (tid < 128)
        s_erow[tid] = s_erow[tid] * scale + ((tid == i) ? 1.0f : 0.0f) + 1e-6f;
    __syncthreads();

    if (tid < 128) s_red[tid] = s_erow[tid];
    __syncthreads();
    for (int st = 64; st > 0; st >>= 1) { if (tid < st) s_red[tid] += s_red[tid + st]; __syncthreads(); }
    const float rsum = s_red[0];
    __syncthreads();

    if (tid < 128) ep_out[row * NN + tid] = s_erow[tid] / rsum;
}

// ---------------- Q/K projection: 4-row tiles, 256 blocks --------------------
__global__ void __launch_bounds__(256)
qk_kernel(const float* __restrict__ vp,
          const float* __restrict__ wq,
          const float* __restrict__ wk,
          float* __restrict__ Q,
          float* __restrict__ K)
{
    __shared__ float vr[4][CC];
    const int rt = blockIdx.x, b = blockIdx.y;
    const int r0 = b * NN + rt * 4;
    const int tid = threadIdx.x;  // 256

    #pragma unroll
    for (int t = 0; t < 2; t++) {
        int idx = tid + t * 256;
        vr[idx >> 7][idx & 127] = vp[r0 * CC + idx];
    }
    __syncthreads();

    const float* wcol = ((tid < 128) ? wq : wk) + (tid & 127);
    float acc[4] = {0.f, 0.f, 0.f, 0.f};
    #pragma unroll 8
    for (int c = 0; c < CC; c++) {
        float wv = __ldg(wcol + c * CC);
        #pragma unroll
        for (int r = 0; r < 4; r++) acc[r] += vr[r][c] * wv;
    }
    float* dst = (tid < 128) ? Q : K;
    #pragma unroll
    for (int r = 0; r < 4; r++) dst[(r0 + r) * CC + (tid & 127)] = acc[r];
}

// ---------------- Fused MHA + D2P: 4 rows/block, grid 256 --------------------
#define KS_STR 132
#define FD_KS    0                          // 128*132 floats; reused as wbuf[2][4096]
#define FD_EDGE  (NN * KS_STR)              // 4*128
#define FD_NF    (FD_EDGE + 4 * NN)         // 4*256
#define FD_HB    (FD_NF + 4 * 2 * CC)       // 4*256
#define FD_AP    (FD_HB + 4 * 2 * CC)       // 2*4*128 attention partials
#define SMEM_FD  ((FD_AP + 2 * 4 * NN) * 4) // bytes

__global__ void __launch_bounds__(256, 2)
mha_d2p_kernel(const float* __restrict__ Q,
               const float* __restrict__ K,
               const float* __restrict__ ep,
               const float* __restrict__ vp,
               const float* __restrict__ w1,
               const float* __restrict__ w2,
               float* __restrict__ vp_out)
{
    extern __shared__ float fsm[];
    float* Ks = fsm + FD_KS;
    float* wb0 = fsm;
    float* wb1 = fsm + 4096;
    float (*edge)[NN]   = (float(*)[NN])(fsm + FD_EDGE);
    float (*nf)[2 * CC] = (float(*)[2 * CC])(fsm + FD_NF);
    float (*hb)[2 * CC] = (float(*)[2 * CC])(fsm + FD_HB);
    float (*attnp)[4][NN] = (float(*)[4][NN])(fsm + FD_AP);
    const int qt = blockIdx.x, b = blockIdx.y;   // qt 0..31
    const int tid = threadIdx.x, w = tid >> 5, lane = tid & 31;
    const int rw = w & 3, half = w >> 2;         // row-in-tile, head-half

    for (int idx = tid; idx < NN * 32; idx += 256) {
        int j = idx >> 5, c4 = (idx & 31) << 2;
        *(float4*)&Ks[j * KS_STR + c4] = *(const float4*)(K + (b * NN + j) * CC + c4);
    }
    const int qi = qt * 4 + rw;
    const int row = b * NN + qi;
    float qreg[2];
    #pragma unroll
    for (int hh = 0; hh < 2; hh++)
        qreg[hh] = Q[row * CC + (half * 2 + hh) * DKK + lane];
    __syncthreads();

    // attention: each warp handles 2 heads of its row; partial sums to smem
    const float inv = 0.17677669529663687f;
    {
        float acc[4] = {0.f, 0.f, 0.f, 0.f};
        #pragma unroll
        for (int hh = 0; hh < 2; hh++) {
            int h = half * 2 + hh;
            float sc[4] = {0.f, 0.f, 0.f, 0.f};
            #pragma unroll
            for (int d4 = 0; d4 < 8; d4++) {
                float q0 = __shfl_sync(0xffffffffu, qreg[hh], d4 * 4);
                float q1 = __shfl_sync(0xffffffffu, qreg[hh], d4 * 4 + 1);
                float q2 = __shfl_sync(0xffffffffu, qreg[hh], d4 * 4 + 2);
                float q3 = __shfl_sync(0xffffffffu, qreg[hh], d4 * 4 + 3);
                #pragma unroll
                for (int kk = 0; kk < 4; kk++) {
                    const float4 kv = *(const float4*)&Ks[(kk * 32 + lane) * KS_STR + h * DKK + d4 * 4];
                    sc[kk] += q0 * kv.x + q1 * kv.y + q2 * kv.z + q3 * kv.w;
                }
            }
            #pragma unroll
            for (int kk = 0; kk < 4; kk++) sc[kk] *= inv;
            float mx = fmaxf(fmaxf(sc[0], sc[1]), fmaxf(sc[2], sc[3]));
            #pragma unroll
            for (int st = 16; st > 0; st >>= 1) mx = fmaxf(mx, __shfl_xor_sync(0xffffffffu, mx, st));
            float ex[4]; float sm = 0.f;
            #pragma unroll
            for (int kk = 0; kk < 4; kk++) { ex[kk] = expf(sc[kk] - mx); sm += ex[kk]; }
            #pragma unroll
            for (int st = 16; st > 0; st >>= 1) sm += __shfl_xor_sync(0xffffffffu, sm, st);
            float r = 1.0f / sm;
            #pragma unroll
            for (int kk = 0; kk < 4; kk++) acc[kk] += ex[kk] * r;
        }
        #pragma unroll
        for (int kk = 0; kk < 4; kk++) attnp[half][rw][kk * 32 + lane] = acc[kk];
    }
    __syncthreads();

    // edge + nf left half (warps 0-3 only)
    if (half == 0) {
        float e[4];
        float ssum = 0.f;
        #pragma unroll
        for (int kk = 0; kk < 4; kk++) {
            int j = kk * 32 + lane;
            float at = attnp[0][rw][j] + attnp[1][rw][j];
            float v = ep[row * NN + j] * (at * 0.25f);
            if (j == qi) v = 0.f;
            e[kk] = v;
            ssum += fabsf(v);
        }
        #pragma unroll
        for (int st = 16; st > 0; st >>= 1) ssum += __shfl_xor_sync(0xffffffffu, ssum, st);
        float rinv = 1.0f / fmaxf(ssum, 1e-12f);
        #pragma unroll
        for (int kk = 0; kk < 4; kk++) {
            int j = kk * 32 + lane;
            edge[rw][j] = e[kk] * rinv;
            nf[rw][j] = vp[row * CC + j];
        }
    }
    __syncthreads();   // attention done; Ks region reusable

    const int c = tid & 127, rr = tid >> 7;   // rows rr, rr+2
    float4 pre[4];

    // ---- aggr: 4 chunks of 32 j-rows of vp[b], double-buffered ----
    {
        const float4* src = (const float4*)(vp + b * NN * CC);
        #pragma unroll
        for (int t = 0; t < 4; t++) pre[t] = __ldg(src + tid + t * 256);
        #pragma unroll
        for (int t = 0; t < 4; t++) *(float4*)&wb0[(tid + t * 256) * 4] = pre[t];
        __syncthreads();

        float a[2] = {0.f, 0.f};
        for (int jc = 0; jc < 4; jc++) {
            float* cur = (jc & 1) ? wb1 : wb0;
            float* nxt = (jc & 1) ? wb0 : wb1;
            if (jc < 3) {
                #pragma unroll
                for (int t = 0; t < 4; t++) pre[t] = __ldg(src + (jc + 1) * 1024 + tid + t * 256);
            }
            #pragma unroll 4
            for (int jj = 0; jj < 32; jj++) {
                float v = cur[jj * 128 + c];
                int j = jc * 32 + jj;
                a[0] += edge[rr][j] * v;
                a[1] += edge[rr + 2][j] * v;
            }
            if (jc < 3) {
                #pragma unroll
                for (int t = 0; t < 4; t++) *(float4*)&nxt[(tid + t * 256) * 4] = pre[t];
            }
            __syncthreads();
        }
        nf[rr][CC + c] = a[0];
        nf[rr + 2][CC + c] = a[1];
    }
    __syncthreads();

    // ---- layer1: 16 chunks of 16 k-rows of w1 [256k x 256o] ----
    {
        const float4* src = (const float4*)w1;
        #pragma unroll
        for (int t = 0; t < 4; t++) pre[t] = __ldg(src + tid + t * 256);
        #pragma unroll
        for (int t = 0; t < 4; t++) *(float4*)&wb0[(tid + t * 256) * 4] = pre[t];
        __syncthreads();

        float accm[4] = {0.f, 0.f, 0.f, 0.f};
        for (int ch = 0; ch < 16; ch++) {
            float* cur = (ch & 1) ? wb1 : wb0;
            float* nxt = (ch & 1) ? wb0 : wb1;
            if (ch < 15) {
                #pragma unroll
                for (int t = 0; t < 4; t++) pre[t] = __ldg(src + (ch + 1) * 1024 + tid + t * 256);
            }
            #pragma unroll 4
            for (int kk = 0; kk < 16; kk++) {
                float wv = cur[kk * 256 + tid];
                int k = ch * 16 + kk;
                #pragma unroll
                for (int r = 0; r < 4; r++) accm[r] += nf[r][k] * wv;
            }
            if (ch < 15) {
                #pragma unroll
                for (int t = 0; t < 4; t++) *(float4*)&nxt[(tid + t * 256) * 4] = pre[t];
            }
            __syncthreads();
        }
        #pragma unroll
        for (int r = 0; r < 4; r++) hb[r][tid] = lrelu(accm[r] * BN_SCALE);
    }
    __syncthreads();

    // ---- layer2: 8 chunks of 32 k-rows of w2 [256k x 128o] ----
    {
        const float4* src = (const float4*)w2;
        #pragma unroll
        for (int t = 0; t < 4; t++) pre[t] = __ldg(src + tid + t * 256);
        #pragma unroll
        for (int t = 0; t < 4; t++) *(float4*)&wb0[(tid + t * 256) * 4] = pre[t];
        __syncthreads();

        float a[2] = {0.f, 0.f};
        for (int ch = 0; ch < 8; ch++) {
            float* cur = (ch & 1) ? wb1 : wb0;
            float* nxt = (ch & 1) ? wb0 : wb1;
            if (ch < 7) {
                #pragma unroll
                for (int t = 0; t < 4; t++) pre[t] = __ldg(src + (ch + 1) * 1024 + tid + t * 256);
            }
            #pragma unroll 4
            for (int kk = 0; kk < 32; kk++) {
                float wv = cur[kk * 128 + c];
                int k = ch * 32 + kk;
                a[0] += hb[rr][k] * wv;
                a[1] += hb[rr + 2][k] * wv;
            }
            if (ch < 7) {
                #pragma unroll
                for (int t = 0; t < 4; t++) *(float4*)&nxt[(tid + t * 256) * 4] = pre[t];
            }
            __syncthreads();
        }
        vp_out[(b * NN + qt * 4 + rr) * CC + c] = lrelu(a[0] * BN_SCALE);
        vp_out[(b * NN + qt * 4 + rr + 2) * CC + c] = lrelu(a[1] * BN_SCALE);
    }
}

// ---------------------------------------------------------------------------

extern "C" void kernel_launch(void* const* d_in, const int* in_sizes, int n_in,
                              void* d_out, int out_size)
{
    const float* vp   = (const float*)d_in[0];
    const float* ep0  = (const float*)d_in[1];
    const float* pw1  = (const float*)d_in[2];
    const float* pw2  = (const float*)d_in[3];
    const float* pw3  = (const float*)d_in[4];
    const float* pb3  = (const float*)d_in[5];
    const float* psw1 = (const float*)d_in[6];
    const float* psw2 = (const float*)d_in[7];
    const float* psw3 = (const float*)d_in[8];
    const float* psb3 = (const float*)d_in[9];
    const float* dw1  = (const float*)d_in[10];
    const float* dw2  = (const float*)d_in[11];
    const float* wq   = (const float*)d_in[12];
    const float* wk   = (const float*)d_in[13];
    float* out = (float*)d_out;

    cudaFuncSetAttribute(psim_mma, cudaFuncAttributeMaxDynamicSharedMemorySize, SMEM_PS);
    cudaFuncSetAttribute(mha_d2p_kernel, cudaFuncAttributeMaxDynamicSharedMemorySize, SMEM_FD);

    float *ep, *Q, *K, *vp1, *vp2;
    uint4 *w1P, *w2P;
    cudaGetSymbolAddress((void**)&ep, g_ep);
    cudaGetSymbolAddress((void**)&Q, g_Q);
    cudaGetSymbolAddress((void**)&K, g_K);
    cudaGetSymbolAddress((void**)&vp1, g_vp1);
    cudaGetSymbolAddress((void**)&vp2, g_vp2);
    cudaGetSymbolAddress((void**)&w1P, g_w1P);
    cudaGetSymbolAddress((void**)&w2P, g_w2P);

    prep_weights_all<<<dim3(16, 3), 256>>>(pw1, pw2, psw1, psw2, w1P, w2P);

    dim3 grid(NN, BB);
    dim3 grid4(32, BB);

    psim_mma<<<grid, 256, SMEM_PS>>>(vp, ep0, ep, w1P, w2P, pw3, pb3, 0);

    for (int g = 0; g < 2; g++) {
        const float* vpc = (g == 0) ? vp : vp1;
        float* vpn = (g == 0) ? vp1 : vp2;

        qk_kernel<<<grid4, 256>>>(vpc, wq + g * CC * CC, wk + g * CC * CC, Q, K);
        mha_d2p_kernel<<<grid4, 256, SMEM_FD>>>(Q, K, ep, vpc,
                                                dw1 + g * 2 * CC * 2 * CC,
                                                dw2 + g * 2 * CC * CC, vpn);

        const int kv = (g == 0) ? 115 : 102;
        float* epo = (g == 1) ? out : ep;
        psim_mma<<<grid, 256, SMEM_PS>>>(vpn, ep, epo,
                                         w1P + (g + 1) * 4096,
                                         w2P + (g + 1) * 4096,
                                         psw3 + g * CC,
                                         psb3 + g, kv);
    }
}

// round 14
// speedup vs baseline: 1.0302x; 1.0302x over previous
#include <cuda_runtime.h>
#include <math.h>
#include <stdint.h>

#define BB 8
#define NN 128
#define CC 128
#define C2 256
#define HH 4
#define DKK 32
#define BN_SCALE 0.9999950000374997f

__device__ float g_ep[BB*NN*NN];
__device__ float g_Q[BB*NN*CC];
__device__ float g_K[BB*NN*CC];
__device__ float g_vp1[BB*NN*CC];
__device__ float g_vp2[BB*NN*CC];
__device__ uint4 g_w1P[3 * 4096];
__device__ uint4 g_w2P[3 * 4096];

__device__ __forceinline__ float lrelu(float x) { return x > 0.f ? x : 0.01f * x; }
__device__ __forceinline__ uint32_t pack_bf16(float lo, float hi) {
    uint32_t r; asm("cvt.rn.bf16x2.f32 %0, %1, %2;" : "=r"(r) : "f"(hi), "f"(lo)); return r;
}

__device__ __forceinline__ void mma_bf16(float* c, const uint4& a, uint32_t b0, uint32_t b1) {
    asm volatile(
        "mma.sync.aligned.m16n8k16.row.col.f32.bf16.bf16.f32 "
        "{%0,%1,%2,%3}, {%4,%5,%6,%7}, {%8,%9}, {%0,%1,%2,%3};"
        : "+f"(c[0]), "+f"(c[1]), "+f"(c[2]), "+f"(c[3])
        : "r"(a.x), "r"(a.y), "r"(a.z), "r"(a.w), "r"(b0), "r"(b1));
}

// ---------------- weight prep ------------------------------------------------
__global__ void prep_weights_all(const float* __restrict__ pw1, const float* __restrict__ pw2,
                                 const float* __restrict__ psw1, const float* __restrict__ psw2,
                                 uint4* __restrict__ w1P, uint4* __restrict__ w2P)
{
    const int set = blockIdx.y;
    const float* w1 = (set == 0) ? pw1 : psw1 + (set - 1) * CC * C2;
    const float* w2 = (set == 0) ? pw2 : psw2 + (set - 1) * C2 * CC;
    uint4* o1 = w1P + set * 4096;
    uint4* o2 = w2P + set * 4096;
    int idx = blockIdx.x * 256 + threadIdx.x;
    {
        int lane = idx & 31, kt = (idx >> 5) & 7, np = (idx >> 8) & 1, ch = idx >> 9;
        int o0 = ch * 32 + np * 16 + (lane >> 2);
        int k0 = kt * 16 + (lane & 3) * 2;
        uint4 v;
        v.x = pack_bf16(w1[k0 * C2 + o0],       w1[(k0 + 1) * C2 + o0]);
        v.y = pack_bf16(w1[(k0 + 8) * C2 + o0], w1[(k0 + 9) * C2 + o0]);
        v.z = pack_bf16(w1[k0 * C2 + o0 + 8],       w1[(k0 + 1) * C2 + o0 + 8]);
        v.w = pack_bf16(w1[(k0 + 8) * C2 + o0 + 8], w1[(k0 + 9) * C2 + o0 + 8]);
        o1[idx] = v;
    }
    {
        int lane = idx & 31, ktl = (idx >> 5) & 7, ntp = (idx >> 8) & 7, kh = idx >> 11;
        int o0 = ntp * 16 + (lane >> 2);
        int k0 = (kh * 8 + ktl) * 16 + (lane & 3) * 2;
        uint4 v;
        v.x = pack_bf16(w2[k0 * CC + o0],       w2[(k0 + 1) * CC + o0]);
        v.y = pack_bf16(w2[(k0 + 8) * CC + o0], w2[(k0 + 9) * CC + o0]);
        v.z = pack_bf16(w2[k0 * CC + o0 + 8],       w2[(k0 + 1) * CC + o0 + 8]);
        v.w = pack_bf16(w2[(k0 + 8) * CC + o0 + 8], w2[(k0 + 9) * CC + o0 + 8]);
        o2[idx] = v;
    }
}

// ---------------- psim via bf16 mma.sync -------------------------------------
#define MS_SIM  0
#define MS_H1   32768
#define MS_VPI  98304
#define MS_W3S  98816
#define MS_EPL  99328
#define MS_EROW 99840
#define MS_RED  100352
#define MS_L3   100864
#define SMEM_PS 101888

__global__ void __launch_bounds__(256, 2)
psim_mma(const float* __restrict__ vp,
         const float* __restrict__ ep_in,
         float* __restrict__ ep_out,
         const uint4* __restrict__ w1P,
         const uint4* __restrict__ w2P,
         const float* __restrict__ w3,
         const float* __restrict__ b3,
         int kval)
{
    extern __shared__ char smem[];
    float* s_vpi  = (float*)(smem + MS_VPI);
    float* s_w3   = (float*)(smem + MS_W3S);
    float* s_epl  = (float*)(smem + MS_EPL);
    float* s_erow = (float*)(smem + MS_EROW);
    float* s_red  = (float*)(smem + MS_RED);
    float* s_l3   = (float*)(smem + MS_L3);
    const int i = blockIdx.x, b = blockIdx.y;
    const int tid = threadIdx.x, w = tid >> 5, lane = tid & 31;
    const int wm = w & 3, wn = w >> 2;
    const int row = b * NN + i;

    if (tid < 128) {
        s_vpi[tid] = vp[row * CC + tid];
        s_w3[tid]  = w3[tid];
        float v = ep_in[row * NN + tid];
        s_epl[tid] = (tid == i) ? 0.f : v;
    }
    __syncthreads();

    for (int q = tid; q < 4096; q += 256) {
        int j = q >> 5, c0 = (q & 31) << 2;
        const float4 vj = *(const float4*)(vp + (b * NN + j) * CC + c0);
        const float4 vi = *(const float4*)(s_vpi + c0);
        float d0 = vi.x - vj.x, d1 = vi.y - vj.y, d2 = vi.z - vj.z, d3 = vi.w - vj.w;
        uint32_t p01 = pack_bf16(d0 * d0, d1 * d1);
        uint32_t p23 = pack_bf16(d2 * d2, d3 * d3);
        int kt = c0 >> 4, mt = j >> 4;
        uint32_t addr = (uint32_t)(((kt * 8 + mt) * 32 + (j & 7) * 4 + ((c0 & 7) >> 1)) * 16
                       + (((j >> 3) & 1) + (((c0 & 15) >> 3) << 1)) * 4);
        *(uint32_t*)(smem + MS_SIM + addr)      = p01;
        *(uint32_t*)(smem + MS_SIM + addr + 16) = p23;
    }
    __syncthreads();

    uint4 Areg[8][2];
    #pragma unroll
    for (int kt = 0; kt < 8; kt++)
        #pragma unroll
        for (int m = 0; m < 2; m++)
            Areg[kt][m] = *(const uint4*)(smem + MS_SIM + ((kt * 8 + wm * 2 + m) * 32 + lane) * 16);
    uint4 pf0 = __ldg(w1P + tid), pf1 = __ldg(w1P + 256 + tid);
    __syncthreads();

    *(uint4*)(smem + MS_SIM + tid * 16) = pf0;
    *(uint4*)(smem + MS_SIM + (256 + tid) * 16) = pf1;
    pf0 = __ldg(w1P + 512 + tid);
    pf1 = __ldg(w1P + 512 + 256 + tid);
    __syncthreads();

    for (int ch = 0; ch < 8; ch++) {
        const char* buf = smem + MS_SIM + (ch & 1) * 8192;
        float acc[2][2][4];
        #pragma unroll
        for (int m = 0; m < 2; m++)
            #pragma unroll
            for (int n = 0; n < 2; n++)
                #pragma unroll
                for (int t = 0; t < 4; t++) acc[m][n][t] = 0.f;
        #pragma unroll
        for (int kt = 0; kt < 8; kt++) {
            uint4 W = *(const uint4*)(buf + ((wn * 8 + kt) * 32 + lane) * 16);
            mma_bf16(acc[0][0], Areg[kt][0], W.x, W.y);
            mma_bf16(acc[0][1], Areg[kt][0], W.z, W.w);
            mma_bf16(acc[1][0], Areg[kt][1], W.x, W.y);
            mma_bf16(acc[1][1], Areg[kt][1], W.z, W.w);
        }
        if (ch < 7) {
            char* nb = smem + MS_SIM + ((ch + 1) & 1) * 8192;
            *(uint4*)(nb + tid * 16) = pf0;
            *(uint4*)(nb + (256 + tid) * 16) = pf1;
            if (ch < 6) {
                pf0 = __ldg(w1P + (ch + 2) * 512 + tid);
                pf1 = __ldg(w1P + (ch + 2) * 512 + 256 + tid);
            }
        }
        #pragma unroll
        for (int m = 0; m < 2; m++)
            #pragma unroll
            for (int ntl = 0; ntl < 2; ntl++) {
                uint2 st;
                st.x = pack_bf16(lrelu(acc[m][ntl][0] * BN_SCALE), lrelu(acc[m][ntl][1] * BN_SCALE));
                st.y = pack_bf16(lrelu(acc[m][ntl][2] * BN_SCALE), lrelu(acc[m][ntl][3] * BN_SCALE));
                uint32_t addr = (uint32_t)((((ch * 2 + wn) * 8 + wm * 2 + m) * 32 + lane) * 16 + ntl * 8);
                *(uint2*)(smem + MS_H1 + addr) = st;
            }
        __syncthreads();
    }

    float acc2[2][8][4];
    #pragma unroll
    for (int m = 0; m < 2; m++)
        #pragma unroll
        for (int n = 0; n < 8; n++)
            #pragma unroll
            for (int t = 0; t < 4; t++) acc2[m][n][t] = 0.f;

    for (int kh = 0; kh < 2; kh++) {
        uint4 pf2[4];
        #pragma unroll
        for (int t = 0; t < 4; t++) pf2[t] = __ldg(w2P + kh * 2048 + tid + t * 256);
        __syncthreads();
        #pragma unroll
        for (int t = 0; t < 4; t++)
            *(uint4*)(smem + MS_SIM + (tid + t * 256) * 16) = pf2[t];
        #pragma unroll
        for (int t = 0; t < 4; t++) pf2[t] = __ldg(w2P + kh * 2048 + 1024 + tid + t * 256);
        #pragma unroll
        for (int t = 0; t < 4; t++)
            *(uint4*)(smem + MS_SIM + (1024 + tid + t * 256) * 16) = pf2[t];
        __syncthreads();
        #pragma unroll 2
        for (int ktl = 0; ktl < 8; ktl++) {
            int kt2 = kh * 8 + ktl;
            uint4 A0 = *(const uint4*)(smem + MS_H1 + ((kt2 * 8 + wm * 2) * 32 + lane) * 16);
            uint4 A1 = *(const uint4*)(smem + MS_H1 + ((kt2 * 8 + wm * 2 + 1) * 32 + lane) * 16);
            #pragma unroll
            for (int pp = 0; pp < 4; pp++) {
                uint4 W = *(const uint4*)(smem + MS_SIM + (((wn * 4 + pp) * 8 + ktl) * 32 + lane) * 16);
                int q = pp * 2;
                mma_bf16(acc2[0][q],     A0, W.x, W.y);
                mma_bf16(acc2[0][q + 1], A0, W.z, W.w);
                mma_bf16(acc2[1][q],     A1, W.x, W.y);
                mma_bf16(acc2[1][q + 1], A1, W.z, W.w);
            }
        }
    }

    const float b3v = b3[0];
    float pr[4] = {0.f, 0.f, 0.f, 0.f};
    #pragma unroll
    for (int m = 0; m < 2; m++)
        #pragma unroll
        for (int q = 0; q < 8; q++) {
            int o = wn * 64 + q * 8 + (lane & 3) * 2;
            float wa = s_w3[o], wb = s_w3[o + 1];
            pr[m * 2]     += lrelu(acc2[m][q][0] * BN_SCALE) * wa + lrelu(acc2[m][q][1] * BN_SCALE) * wb;
            pr[m * 2 + 1] += lrelu(acc2[m][q][2] * BN_SCALE) * wa + lrelu(acc2[m][q][3] * BN_SCALE) * wb;
        }
    #pragma unroll
    for (int t = 0; t < 4; t++) {
        pr[t] += __shfl_xor_sync(0xffffffffu, pr[t], 1);
        pr[t] += __shfl_xor_sync(0xffffffffu, pr[t], 2);
    }
    if ((lane & 3) == 0) {
        int g = lane >> 2;
        s_l3[wn * 128 + wm * 32 + g]      = pr[0];
        s_l3[wn * 128 + wm * 32 + g + 8]  = pr[1];
        s_l3[wn * 128 + wm * 32 + g + 16] = pr[2];
        s_l3[wn * 128 + wm * 32 + g + 24] = pr[3];
    }
    __syncthreads();
    if (tid < 128) {
        float e = s_l3[tid] + s_l3[128 + tid];
        s_erow[tid] = 1.0f / (1.0f + expf(-(e + b3v)));
    }
    __syncthreads();

    // ---- row postprocess (warp-shuffle reductions) ----
    if (tid < 128) s_erow[tid] *= s_epl[tid];
    __syncthreads();

    if (w == 0) {
        float v = s_epl[lane] + s_epl[lane + 32] + s_epl[lane + 64] + s_epl[lane + 96];
        #pragma unroll
        for (int st = 16; st > 0; st >>= 1) v += __shfl_xor_sync(0xffffffffu, v, st);
        if (lane == 0) s_red[0] = v;
    }
    int cnt = 0;
    if (kval > 0 && tid < 128) {
        float mine = s_erow[tid];
        for (int jj = 0; jj < NN; jj++) {
            float vv = s_erow[jj];
            cnt += (vv > mine) || (vv == mine && jj < tid);
        }
    }
    __syncthreads();
    if (kval > 0 && tid < 128 && cnt >= kval) s_erow[tid] = 0.f;
    __syncthreads();

    if (w == 0) {
        float v = fabsf(s_erow[lane]) + fabsf(s_erow[lane + 32])
                + fabsf(s_erow[lane + 64]) + fabsf(s_erow[lane + 96]);
        #pragma unroll
        for (int st = 16; st > 0; st >>= 1) v += __shfl_xor_sync(0xffffffffu, v, st);
        if (lane == 0) s_red[1] = v;
    }
    __syncthreads();

    const float scale = s_red[0] / fmaxf(s_red[1], 1e-12f);
    if (tid < 128)
        s_erow[tid] = s_erow[tid] * scale + ((tid == i) ? 1.0f : 0.0f) + 1e-6f;
    __syncthreads();

    if (w == 0) {
        float v = s_erow[lane] + s_erow[lane + 32] + s_erow[lane + 64] + s_erow[lane + 96];
        #pragma unroll
        for (int st = 16; st > 0; st >>= 1) v += __shfl_xor_sync(0xffffffffu, v, st);
        if (lane == 0) s_red[2] = v;
    }
    __syncthreads();

    if (tid < 128) ep_out[row * NN + tid] = s_erow[tid] / s_red[2];
}

// ---------------- Q/K projection: 8-row tiles --------------------------------
__global__ void __launch_bounds__(256)
qk_kernel(const float* __restrict__ vp,
          const float* __restrict__ wq,
          const float* __restrict__ wk,
          float* __restrict__ Q,
          float* __restrict__ K)
{
    __shared__ float vr[8][CC];
    const int rt = blockIdx.x, b = blockIdx.y;
    const int r0 = b * NN + rt * 8;
    const int tid = threadIdx.x;

    #pragma unroll
    for (int t = 0; t < 4; t++) {
        int idx = tid + t * 256;
        vr[idx >> 7][idx & 127] = vp[r0 * CC + idx];
    }
    __syncthreads();

    const float* wcol = ((tid < 128) ? wq : wk) + (tid & 127);
    float acc[8] = {0.f};
    #pragma unroll 8
    for (int c = 0; c < CC; c++) {
        float wv = __ldg(wcol + c * CC);
        #pragma unroll
        for (int r = 0; r < 8; r++) acc[r] += vr[r][c] * wv;
    }
    float* dst = (tid < 128) ? Q : K;
    #pragma unroll
    for (int r = 0; r < 8; r++) dst[(r0 + r) * CC + (tid & 127)] = acc[r];
}

// ---------------- Fused MHA + D2P: 8 rows/block, deep-pipelined --------------
#define KS_STR 132
#define FD_KS    0                          // 16896 floats; reused as 3x4096 wbufs
#define FD_EDGE  (NN * KS_STR)              // 8*128
#define FD_NF    (FD_EDGE + 8 * NN)         // 8*256
#define FD_HB    (FD_NF + 8 * 2 * CC)       // 8*256
#define SMEM_FD  ((FD_HB + 8 * 2 * CC) * 4) // 88064 bytes

#define LDG_CH(dst, src, chn) { \
    const float4* _p = (src) + (chn) * 1024 + tid; \
    dst[0] = __ldg(_p); dst[1] = __ldg(_p + 256); \
    dst[2] = __ldg(_p + 512); dst[3] = __ldg(_p + 768); }
#define STS_CH(bufidx, src4) { \
    float* _b = fsm + (bufidx) * 4096; \
    *(float4*)&_b[(tid)*4]        = src4[0]; \
    *(float4*)&_b[(tid+256)*4]    = src4[1]; \
    *(float4*)&_b[(tid+512)*4]    = src4[2]; \
    *(float4*)&_b[(tid+768)*4]    = src4[3]; }

__global__ void __launch_bounds__(256)
mha_d2p_kernel(const float* __restrict__ Q,
               const float* __restrict__ K,
               const float* __restrict__ ep,
               const float* __restrict__ vp,
               const float* __restrict__ w1,
               const float* __restrict__ w2,
               float* __restrict__ vp_out)
{
    extern __shared__ float fsm[];
    float* Ks = fsm + FD_KS;
    float (*edge)[NN]   = (float(*)[NN])(fsm + FD_EDGE);
    float (*nf)[2 * CC] = (float(*)[2 * CC])(fsm + FD_NF);
    float (*hb)[2 * CC] = (float(*)[2 * CC])(fsm + FD_HB);
    const int qt = blockIdx.x, b = blockIdx.y;   // qt 0..15
    const int tid = threadIdx.x, w = tid >> 5, lane = tid & 31;

    for (int idx = tid; idx < NN * 32; idx += 256) {
        int j = idx >> 5, c4 = (idx & 31) << 2;
        *(float4*)&Ks[j * KS_STR + c4] = *(const float4*)(K + (b * NN + j) * CC + c4);
    }
    const int qi = qt * 8 + w;
    const int row = b * NN + qi;
    float qreg[4];
    #pragma unroll
    for (int h = 0; h < HH; h++) qreg[h] = Q[row * CC + h * DKK + lane];

    // early prefetch of aggr chunks 0,1 (vp[b])
    const float4* vsrc = (const float4*)(vp + b * NN * CC);
    float4 pA[4], pB[4];
    LDG_CH(pA, vsrc, 0);
    LDG_CH(pB, vsrc, 1);
    __syncthreads();

    // ---- attention (8 warps, 1 row each, all 4 heads) ----
    const float inv = 0.17677669529663687f;
    float acc[4] = {0.f, 0.f, 0.f, 0.f};
    #pragma unroll
    for (int h = 0; h < HH; h++) {
        float sc[4] = {0.f, 0.f, 0.f, 0.f};
        #pragma unroll
        for (int d4 = 0; d4 < 8; d4++) {
            float q0 = __shfl_sync(0xffffffffu, qreg[h], d4 * 4);
            float q1 = __shfl_sync(0xffffffffu, qreg[h], d4 * 4 + 1);
            float q2 = __shfl_sync(0xffffffffu, qreg[h], d4 * 4 + 2);
            float q3 = __shfl_sync(0xffffffffu, qreg[h], d4 * 4 + 3);
            #pragma unroll
            for (int kk = 0; kk < 4; kk++) {
                const float4 kv = *(const float4*)&Ks[(kk * 32 + lane) * KS_STR + h * DKK + d4 * 4];
                sc[kk] += q0 * kv.x + q1 * kv.y + q2 * kv.z + q3 * kv.w;
            }
        }
        #pragma unroll
        for (int kk = 0; kk < 4; kk++) sc[kk] *= inv;
        float mx = fmaxf(fmaxf(sc[0], sc[1]), fmaxf(sc[2], sc[3]));
        #pragma unroll
        for (int st = 16; st > 0; st >>= 1) mx = fmaxf(mx, __shfl_xor_sync(0xffffffffu, mx, st));
        float ex[4]; float sm = 0.f;
        #pragma unroll
        for (int kk = 0; kk < 4; kk++) { ex[kk] = expf(sc[kk] - mx); sm += ex[kk]; }
        #pragma unroll
        for (int st = 16; st > 0; st >>= 1) sm += __shfl_xor_sync(0xffffffffu, sm, st);
        float r = 1.0f / sm;
        #pragma unroll
        for (int kk = 0; kk < 4; kk++) acc[kk] += ex[kk] * r;
    }

    // ---- edge + nf left half ----
    {
        float e[4];
        float ssum = 0.f;
        #pragma unroll
        for (int kk = 0; kk < 4; kk++) {
            int j = kk * 32 + lane;
            float v = ep[row * NN + j] * (acc[kk] * 0.25f);
            if (j == qi) v = 0.f;
            e[kk] = v;
            ssum += fabsf(v);
        }
        #pragma unroll
        for (int st = 16; st > 0; st >>= 1) ssum += __shfl_xor_sync(0xffffffffu, ssum, st);
        float rinv = 1.0f / fmaxf(ssum, 1e-12f);
        #pragma unroll
        for (int kk = 0; kk < 4; kk++) {
            int j = kk * 32 + lane;
            edge[w][j] = e[kk] * rinv;
            nf[w][j] = vp[row * CC + j];
        }
    }
    __syncthreads();   // attention reads of Ks done -> wbufs usable

    const int c = tid & 127, rr = tid >> 7;   // rows rr + 2q

    // ---- aggr: NCH=4 chunks of 32 j-rows, 3-buffer pipeline ----
    {
        STS_CH(0, pA);
        LDG_CH(pA, vsrc, 2);
        __syncthreads();
        STS_CH(1, pB);
        LDG_CH(pB, vsrc, 3);

        float a[4] = {0.f, 0.f, 0.f, 0.f};
        for (int jc = 0; jc < 4; jc++) {
            const float* cur = fsm + (jc % 3) * 4096;
            #pragma unroll 4
            for (int jj = 0; jj < 32; jj++) {
                float v = cur[jj * 128 + c];
                int j = jc * 32 + jj;
                #pragma unroll
                for (int q = 0; q < 4; q++) a[q] += edge[rr + 2 * q][j] * v;
            }
            __syncthreads();
            if (jc + 2 < 4) {
                if (jc & 1) { STS_CH((jc + 2) % 3, pB); }
                else        { STS_CH((jc + 2) % 3, pA); }
            }
        }
        #pragma unroll
        for (int q = 0; q < 4; q++) nf[rr + 2 * q][CC + c] = a[q];
    }
    // prefetch layer1 chunks 0,1 before the sync
    const float4* w1v = (const float4*)w1;
    LDG_CH(pA, w1v, 0);
    LDG_CH(pB, w1v, 1);
    __syncthreads();   // nf complete; aggr bufs free

    // ---- layer1: NCH=16 chunks of 16 k-rows of w1 ----
    {
        STS_CH(0, pA);
        LDG_CH(pA, w1v, 2);
        __syncthreads();
        STS_CH(1, pB);
        LDG_CH(pB, w1v, 3);

        float accm[8] = {0.f};
        for (int ch = 0; ch < 16; ch++) {
            const float* cur = fsm + (ch % 3) * 4096;
            #pragma unroll 4
            for (int kk = 0; kk < 16; kk++) {
                float wv = cur[kk * 256 + tid];
                int k = ch * 16 + kk;
                #pragma unroll
                for (int r = 0; r < 8; r++) accm[r] += nf[r][k] * wv;
            }
            __syncthreads();
            if (ch + 2 < 16) {
                if (ch & 1) { STS_CH((ch + 2) % 3, pB); }
                else        { STS_CH((ch + 2) % 3, pA); }
            }
            if (ch + 4 < 16) {
                if (ch & 1) { LDG_CH(pB, w1v, ch + 4); }
                else        { LDG_CH(pA, w1v, ch + 4); }
            }
        }
        #pragma unroll
        for (int r = 0; r < 8; r++) hb[r][tid] = lrelu(accm[r] * BN_SCALE);
    }
    // prefetch layer2 chunks 0,1 before the sync
    const float4* w2v = (const float4*)w2;
    LDG_CH(pA, w2v, 0);
    LDG_CH(pB, w2v, 1);
    __syncthreads();   // hb complete; layer1 bufs free

    // ---- layer2: NCH=8 chunks of 32 k-rows of w2 ----
    {
        STS_CH(0, pA);
        LDG_CH(pA, w2v, 2);
        __syncthreads();
        STS_CH(1, pB);
        LDG_CH(pB, w2v, 3);

        float a[4] = {0.f, 0.f, 0.f, 0.f};
        for (int ch = 0; ch < 8; ch++) {
            const float* cur = fsm + (ch % 3) * 4096;
            #pragma unroll 4
            for (int kk = 0; kk < 32; kk++) {
                float wv = cur[kk * 128 + c];
                int k = ch * 32 + kk;
                #pragma unroll
                for (int q = 0; q < 4; q++) a[q] += hb[rr + 2 * q][k] * wv;
            }
            __syncthreads();
            if (ch + 2 < 8) {
                if (ch & 1) { STS_CH((ch + 2) % 3, pB); }
                else        { STS_CH((ch + 2) % 3, pA); }
            }
            if (ch + 4 < 8) {
                if (ch & 1) { LDG_CH(pB, w2v, ch + 4); }
                else        { LDG_CH(pA, w2v, ch + 4); }
            }
        }
        #pragma unroll
        for (int q = 0; q < 4; q++)
            vp_out[(b * NN + qt * 8 + rr + 2 * q) * CC + c] = lrelu(a[q] * BN_SCALE);
    }
}

// ---------------------------------------------------------------------------

extern "C" void kernel_launch(void* const* d_in, const int* in_sizes, int n_in,
                              void* d_out, int out_size)
{
    const float* vp   = (const float*)d_in[0];
    const float* ep0  = (const float*)d_in[1];
    const float* pw1  = (const float*)d_in[2];
    const float* pw2  = (const float*)d_in[3];
    const float* pw3  = (const float*)d_in[4];
    const float* pb3  = (const float*)d_in[5];
    const float* psw1 = (const float*)d_in[6];
    const float* psw2 = (const float*)d_in[7];
    const float* psw3 = (const float*)d_in[8];
    const float* psb3 = (const float*)d_in[9];
    const float* dw1  = (const float*)d_in[10];
    const float* dw2  = (const float*)d_in[11];
    const float* wq   = (const float*)d_in[12];
    const float* wk   = (const float*)d_in[13];
    float* out = (float*)d_out;

    cudaFuncSetAttribute(psim_mma, cudaFuncAttributeMaxDynamicSharedMemorySize, SMEM_PS);
    cudaFuncSetAttribute(mha_d2p_kernel, cudaFuncAttributeMaxDynamicSharedMemorySize, SMEM_FD);

    float *ep, *Q, *K, *vp1, *vp2;
    uint4 *w1P, *w2P;
    cudaGetSymbolAddress((void**)&ep, g_ep);
    cudaGetSymbolAddress((void**)&Q, g_Q);
    cudaGetSymbolAddress((void**)&K, g_K);
    cudaGetSymbolAddress((void**)&vp1, g_vp1);
    cudaGetSymbolAddress((void**)&vp2, g_vp2);
    cudaGetSymbolAddress((void**)&w1P, g_w1P);
    cudaGetSymbolAddress((void**)&w2P, g_w2P);

    prep_weights_all<<<dim3(16, 3), 256>>>(pw1, pw2, psw1, psw2, w1P, w2P);

    dim3 grid(NN, BB);
    dim3 grid8(16, BB);

    psim_mma<<<grid, 256, SMEM_PS>>>(vp, ep0, ep, w1P, w2P, pw3, pb3, 0);

    for (int g = 0; g < 2; g++) {
        const float* vpc = (g == 0) ? vp : vp1;
        float* vpn = (g == 0) ? vp1 : vp2;

        qk_kernel<<<grid8, 256>>>(vpc, wq + g * CC * CC, wk + g * CC * CC, Q, K);
        mha_d2p_kernel<<<grid8, 256, SMEM_FD>>>(Q, K, ep, vpc,
                                                dw1 + g * 2 * CC * 2 * CC,
                                                dw2 + g * 2 * CC * CC, vpn);

        const int kv = (g == 0) ? 115 : 102;
        float* epo = (g == 1) ? out : ep;
        psim_mma<<<grid, 256, SMEM_PS>>>(vpn, ep, epo,
                                         w1P + (g + 1) * 4096,
                                         w2P + (g + 1) * 4096,
                                         psw3 + g * CC,
                                         psb3 + g, kv);
    }
}

// round 15
// speedup vs baseline: 1.1226x; 1.0896x over previous
#include <cuda_runtime.h>
#include <math.h>
#include <stdint.h>

#define BB 8
#define NN 128
#define CC 128
#define C2 256
#define HH 4
#define DKK 32
#define BN_SCALE 0.9999950000374997f

__device__ float g_ep[BB*NN*NN];
__device__ float g_Q[BB*NN*CC];
__device__ float g_K[BB*NN*CC];
__device__ float g_vp1[BB*NN*CC];
__device__ float g_vp2[BB*NN*CC];
__device__ uint4 g_w1P[3 * 4096];
__device__ uint4 g_w2P[3 * 4096];

__device__ __forceinline__ float lrelu(float x) { return x > 0.f ? x : 0.01f * x; }
__device__ __forceinline__ uint32_t pack_bf16(float lo, float hi) {
    uint32_t r; asm("cvt.rn.bf16x2.f32 %0, %1, %2;" : "=r"(r) : "f"(hi), "f"(lo)); return r;
}

__device__ __forceinline__ void mma_bf16(float* c, const uint4& a, uint32_t b0, uint32_t b1) {
    asm volatile(
        "mma.sync.aligned.m16n8k16.row.col.f32.bf16.bf16.f32 "
        "{%0,%1,%2,%3}, {%4,%5,%6,%7}, {%8,%9}, {%0,%1,%2,%3};"
        : "+f"(c[0]), "+f"(c[1]), "+f"(c[2]), "+f"(c[3])
        : "r"(a.x), "r"(a.y), "r"(a.z), "r"(a.w), "r"(b0), "r"(b1));
}

// ---- cp.async helpers ----
#define CPA16(dst_smem, gptr) \
    asm volatile("cp.async.cg.shared.global [%0], [%1], 16;" :: "r"(dst_smem), "l"(gptr) : "memory")
#define CPA_COMMIT() asm volatile("cp.async.commit_group;" ::: "memory")
#define CPA_WAIT0()  asm volatile("cp.async.wait_group 0;" ::: "memory")
#define CPA_WAIT1()  asm volatile("cp.async.wait_group 1;" ::: "memory")
#define CPA_WAIT2()  asm volatile("cp.async.wait_group 2;" ::: "memory")

// ---------------- weight prep ------------------------------------------------
__global__ void prep_weights_all(const float* __restrict__ pw1, const float* __restrict__ pw2,
                                 const float* __restrict__ psw1, const float* __restrict__ psw2,
                                 uint4* __restrict__ w1P, uint4* __restrict__ w2P)
{
    const int set = blockIdx.y;
    const float* w1 = (set == 0) ? pw1 : psw1 + (set - 1) * CC * C2;
    const float* w2 = (set == 0) ? pw2 : psw2 + (set - 1) * C2 * CC;
    uint4* o1 = w1P + set * 4096;
    uint4* o2 = w2P + set * 4096;
    int idx = blockIdx.x * 256 + threadIdx.x;
    {
        int lane = idx & 31, kt = (idx >> 5) & 7, np = (idx >> 8) & 1, ch = idx >> 9;
        int o0 = ch * 32 + np * 16 + (lane >> 2);
        int k0 = kt * 16 + (lane & 3) * 2;
        uint4 v;
        v.x = pack_bf16(w1[k0 * C2 + o0],       w1[(k0 + 1) * C2 + o0]);
        v.y = pack_bf16(w1[(k0 + 8) * C2 + o0], w1[(k0 + 9) * C2 + o0]);
        v.z = pack_bf16(w1[k0 * C2 + o0 + 8],       w1[(k0 + 1) * C2 + o0 + 8]);
        v.w = pack_bf16(w1[(k0 + 8) * C2 + o0 + 8], w1[(k0 + 9) * C2 + o0 + 8]);
        o1[idx] = v;
    }
    {
        int lane = idx & 31, ktl = (idx >> 5) & 7, ntp = (idx >> 8) & 7, kh = idx >> 11;
        int o0 = ntp * 16 + (lane >> 2);
        int k0 = (kh * 8 + ktl) * 16 + (lane & 3) * 2;
        uint4 v;
        v.x = pack_bf16(w2[k0 * CC + o0],       w2[(k0 + 1) * CC + o0]);
        v.y = pack_bf16(w2[(k0 + 8) * CC + o0], w2[(k0 + 9) * CC + o0]);
        v.z = pack_bf16(w2[k0 * CC + o0 + 8],       w2[(k0 + 1) * CC + o0 + 8]);
        v.w = pack_bf16(w2[(k0 + 8) * CC + o0 + 8], w2[(k0 + 9) * CC + o0 + 8]);
        o2[idx] = v;
    }
}

// ---------------- psim via bf16 mma.sync -------------------------------------
#define MS_SIM  0
#define MS_H1   32768
#define MS_VPI  98304
#define MS_W3S  98816
#define MS_EPL  99328
#define MS_EROW 99840
#define MS_RED  100352
#define MS_L3   100864
#define SMEM_PS 101888

__global__ void __launch_bounds__(256, 2)
psim_mma(const float* __restrict__ vp,
         const float* __restrict__ ep_in,
         float* __restrict__ ep_out,
         const uint4* __restrict__ w1P,
         const uint4* __restrict__ w2P,
         const float* __restrict__ w3,
         const float* __restrict__ b3,
         int kval)
{
    extern __shared__ char smem[];
    uint32_t sbase;
    asm("{ .reg .u64 t; cvta.to.shared.u64 t, %1; cvt.u32.u64 %0, t; }" : "=r"(sbase) : "l"(smem));
    float* s_vpi  = (float*)(smem + MS_VPI);
    float* s_w3   = (float*)(smem + MS_W3S);
    float* s_epl  = (float*)(smem + MS_EPL);
    float* s_erow = (float*)(smem + MS_EROW);
    float* s_red  = (float*)(smem + MS_RED);
    float* s_l3   = (float*)(smem + MS_L3);
    const int i = blockIdx.x, b = blockIdx.y;
    const int tid = threadIdx.x, w = tid >> 5, lane = tid & 31;
    const int wm = w & 3, wn = w >> 2;
    const int row = b * NN + i;

    if (tid < 128) {
        s_vpi[tid] = vp[row * CC + tid];
        s_w3[tid]  = w3[tid];
        float v = ep_in[row * NN + tid];
        s_epl[tid] = (tid == i) ? 0.f : v;
    }
    __syncthreads();

    for (int q = tid; q < 4096; q += 256) {
        int j = q >> 5, c0 = (q & 31) << 2;
        const float4 vj = *(const float4*)(vp + (b * NN + j) * CC + c0);
        const float4 vi = *(const float4*)(s_vpi + c0);
        float d0 = vi.x - vj.x, d1 = vi.y - vj.y, d2 = vi.z - vj.z, d3 = vi.w - vj.w;
        uint32_t p01 = pack_bf16(d0 * d0, d1 * d1);
        uint32_t p23 = pack_bf16(d2 * d2, d3 * d3);
        int kt = c0 >> 4, mt = j >> 4;
        uint32_t addr = (uint32_t)(((kt * 8 + mt) * 32 + (j & 7) * 4 + ((c0 & 7) >> 1)) * 16
                       + (((j >> 3) & 1) + (((c0 & 15) >> 3) << 1)) * 4);
        *(uint32_t*)(smem + MS_SIM + addr)      = p01;
        *(uint32_t*)(smem + MS_SIM + addr + 16) = p23;
    }
    __syncthreads();

    uint4 Areg[8][2];
    #pragma unroll
    for (int kt = 0; kt < 8; kt++)
        #pragma unroll
        for (int m = 0; m < 2; m++)
            Areg[kt][m] = *(const uint4*)(smem + MS_SIM + ((kt * 8 + wm * 2 + m) * 32 + lane) * 16);
    uint4 pf0 = __ldg(w1P + tid), pf1 = __ldg(w1P + 256 + tid);
    __syncthreads();

    *(uint4*)(smem + MS_SIM + tid * 16) = pf0;
    *(uint4*)(smem + MS_SIM + (256 + tid) * 16) = pf1;
    pf0 = __ldg(w1P + 512 + tid);
    pf1 = __ldg(w1P + 512 + 256 + tid);
    __syncthreads();

    for (int ch = 0; ch < 8; ch++) {
        const char* buf = smem + MS_SIM + (ch & 1) * 8192;
        float acc[2][2][4];
        #pragma unroll
        for (int m = 0; m < 2; m++)
            #pragma unroll
            for (int n = 0; n < 2; n++)
                #pragma unroll
                for (int t = 0; t < 4; t++) acc[m][n][t] = 0.f;
        #pragma unroll
        for (int kt = 0; kt < 8; kt++) {
            uint4 W = *(const uint4*)(buf + ((wn * 8 + kt) * 32 + lane) * 16);
            mma_bf16(acc[0][0], Areg[kt][0], W.x, W.y);
            mma_bf16(acc[0][1], Areg[kt][0], W.z, W.w);
            mma_bf16(acc[1][0], Areg[kt][1], W.x, W.y);
            mma_bf16(acc[1][1], Areg[kt][1], W.z, W.w);
        }
        if (ch < 7) {
            char* nb = smem + MS_SIM + ((ch + 1) & 1) * 8192;
            *(uint4*)(nb + tid * 16) = pf0;
            *(uint4*)(nb + (256 + tid) * 16) = pf1;
            if (ch < 6) {
                pf0 = __ldg(w1P + (ch + 2) * 512 + tid);
                pf1 = __ldg(w1P + (ch + 2) * 512 + 256 + tid);
            }
        }
        #pragma unroll
        for (int m = 0; m < 2; m++)
            #pragma unroll
            for (int ntl = 0; ntl < 2; ntl++) {
                uint2 st;
                st.x = pack_bf16(lrelu(acc[m][ntl][0] * BN_SCALE), lrelu(acc[m][ntl][1] * BN_SCALE));
                st.y = pack_bf16(lrelu(acc[m][ntl][2] * BN_SCALE), lrelu(acc[m][ntl][3] * BN_SCALE));
                uint32_t addr = (uint32_t)((((ch * 2 + wn) * 8 + wm * 2 + m) * 32 + lane) * 16 + ntl * 8);
                *(uint2*)(smem + MS_H1 + addr) = st;
            }
        __syncthreads();
    }

    float acc2[2][8][4];
    #pragma unroll
    for (int m = 0; m < 2; m++)
        #pragma unroll
        for (int n = 0; n < 8; n++)
            #pragma unroll
            for (int t = 0; t < 4; t++) acc2[m][n][t] = 0.f;

    for (int kh = 0; kh < 2; kh++) {
        // stage 32KB of w2P via cp.async (no register staging)
        {
            uint32_t dstb = sbase + MS_SIM + tid * 16;
            const uint4* g = w2P + kh * 2048 + tid;
            #pragma unroll
            for (int t = 0; t < 8; t++) CPA16(dstb + t * 4096, (const void*)(g + t * 256));
            CPA_COMMIT();
            CPA_WAIT0();
        }
        __syncthreads();
        #pragma unroll 2
        for (int ktl = 0; ktl < 8; ktl++) {
            int kt2 = kh * 8 + ktl;
            uint4 A0 = *(const uint4*)(smem + MS_H1 + ((kt2 * 8 + wm * 2) * 32 + lane) * 16);
            uint4 A1 = *(const uint4*)(smem + MS_H1 + ((kt2 * 8 + wm * 2 + 1) * 32 + lane) * 16);
            #pragma unroll
            for (int pp = 0; pp < 4; pp++) {
                uint4 W = *(const uint4*)(smem + MS_SIM + (((wn * 4 + pp) * 8 + ktl) * 32 + lane) * 16);
                int q = pp * 2;
                mma_bf16(acc2[0][q],     A0, W.x, W.y);
                mma_bf16(acc2[0][q + 1], A0, W.z, W.w);
                mma_bf16(acc2[1][q],     A1, W.x, W.y);
                mma_bf16(acc2[1][q + 1], A1, W.z, W.w);
            }
        }
        __syncthreads();
    }

    const float b3v = b3[0];
    float pr[4] = {0.f, 0.f, 0.f, 0.f};
    #pragma unroll
    for (int m = 0; m < 2; m++)
        #pragma unroll
        for (int q = 0; q < 8; q++) {
            int o = wn * 64 + q * 8 + (lane & 3) * 2;
            float wa = s_w3[o], wb = s_w3[o + 1];
            pr[m * 2]     += lrelu(acc2[m][q][0] * BN_SCALE) * wa + lrelu(acc2[m][q][1] * BN_SCALE) * wb;
            pr[m * 2 + 1] += lrelu(acc2[m][q][2] * BN_SCALE) * wa + lrelu(acc2[m][q][3] * BN_SCALE) * wb;
        }
    #pragma unroll
    for (int t = 0; t < 4; t++) {
        pr[t] += __shfl_xor_sync(0xffffffffu, pr[t], 1);
        pr[t] += __shfl_xor_sync(0xffffffffu, pr[t], 2);
    }
    if ((lane & 3) == 0) {
        int g = lane >> 2;
        s_l3[wn * 128 + wm * 32 + g]      = pr[0];
        s_l3[wn * 128 + wm * 32 + g + 8]  = pr[1];
        s_l3[wn * 128 + wm * 32 + g + 16] = pr[2];
        s_l3[wn * 128 + wm * 32 + g + 24] = pr[3];
    }
    __syncthreads();
    if (tid < 128) {
        float e = s_l3[tid] + s_l3[128 + tid];
        s_erow[tid] = 1.0f / (1.0f + expf(-(e + b3v)));
    }
    __syncthreads();

    // ---- row postprocess (warp-shuffle reductions) ----
    if (tid < 128) s_erow[tid] *= s_epl[tid];
    __syncthreads();

    if (w == 0) {
        float v = s_epl[lane] + s_epl[lane + 32] + s_epl[lane + 64] + s_epl[lane + 96];
        #pragma unroll
        for (int st = 16; st > 0; st >>= 1) v += __shfl_xor_sync(0xffffffffu, v, st);
        if (lane == 0) s_red[0] = v;
    }
    int cnt = 0;
    if (kval > 0 && tid < 128) {
        float mine = s_erow[tid];
        for (int jj = 0; jj < NN; jj++) {
            float vv = s_erow[jj];
            cnt += (vv > mine) || (vv == mine && jj < tid);
        }
    }
    __syncthreads();
    if (kval > 0 && tid < 128 && cnt >= kval) s_erow[tid] = 0.f;
    __syncthreads();

    if (w == 0) {
        float v = fabsf(s_erow[lane]) + fabsf(s_erow[lane + 32])
                + fabsf(s_erow[lane + 64]) + fabsf(s_erow[lane + 96]);
        #pragma unroll
        for (int st = 16; st > 0; st >>= 1) v += __shfl_xor_sync(0xffffffffu, v, st);
        if (lane == 0) s_red[1] = v;
    }
    __syncthreads();

    const float scale = s_red[0] / fmaxf(s_red[1], 1e-12f);
    if (tid < 128)
        s_erow[tid] = s_erow[tid] * scale + ((tid == i) ? 1.0f : 0.0f) + 1e-6f;
    __syncthreads();

    if (w == 0) {
        float v = s_erow[lane] + s_erow[lane + 32] + s_erow[lane + 64] + s_erow[lane + 96];
        #pragma unroll
        for (int st = 16; st > 0; st >>= 1) v += __shfl_xor_sync(0xffffffffu, v, st);
        if (lane == 0) s_red[2] = v;
    }
    __syncthreads();

    if (tid < 128) ep_out[row * NN + tid] = s_erow[tid] / s_red[2];
}

// ---------------- Q/K projection: 8-row tiles --------------------------------
__global__ void __launch_bounds__(256)
qk_kernel(const float* __restrict__ vp,
          const float* __restrict__ wq,
          const float* __restrict__ wk,
          float* __restrict__ Q,
          float* __restrict__ K)
{
    __shared__ float vr[8][CC];
    const int rt = blockIdx.x, b = blockIdx.y;
    const int r0 = b * NN + rt * 8;
    const int tid = threadIdx.x;

    #pragma unroll
    for (int t = 0; t < 4; t++) {
        int idx = tid + t * 256;
        vr[idx >> 7][idx & 127] = vp[r0 * CC + idx];
    }
    __syncthreads();

    const float* wcol = ((tid < 128) ? wq : wk) + (tid & 127);
    float acc[8] = {0.f};
    #pragma unroll 8
    for (int c = 0; c < CC; c++) {
        float wv = __ldg(wcol + c * CC);
        #pragma unroll
        for (int r = 0; r < 8; r++) acc[r] += vr[r][c] * wv;
    }
    float* dst = (tid < 128) ? Q : K;
    #pragma unroll
    for (int r = 0; r < 8; r++) dst[(r0 + r) * CC + (tid & 127)] = acc[r];
}

// ---------------- Fused MHA + D2P: cp.async 4-buffer pipelines ---------------
#define KS_STR 132
#define FD_KS    0                          // Ks 16896 floats; overlaps 4x4096 wbufs
#define FD_EDGE  (NN * KS_STR)
#define FD_NF    (FD_EDGE + 8 * NN)
#define FD_HB    (FD_NF + 8 * 2 * CC)
#define SMEM_FD  ((FD_HB + 8 * 2 * CC) * 4) // 88064 bytes

// issue one 16KB chunk (4096 floats) into wbuf[bufidx] via cp.async + commit
#define ISSUE_CH(bufidx, srcf4, chn) { \
    const float4* _g = (srcf4) + (chn) * 1024 + tid; \
    uint32_t _d = sbase + (uint32_t)(bufidx) * 16384u + (uint32_t)tid * 16u; \
    CPA16(_d, (const void*)_g); \
    CPA16(_d + 4096u, (const void*)(_g + 256)); \
    CPA16(_d + 8192u, (const void*)(_g + 512)); \
    CPA16(_d + 12288u, (const void*)(_g + 768)); \
    CPA_COMMIT(); }

__global__ void __launch_bounds__(256)
mha_d2p_kernel(const float* __restrict__ Q,
               const float* __restrict__ K,
               const float* __restrict__ ep,
               const float* __restrict__ vp,
               const float* __restrict__ w1,
               const float* __restrict__ w2,
               float* __restrict__ vp_out)
{
    extern __shared__ float fsm[];
    uint32_t sbase;
    asm("{ .reg .u64 t; cvta.to.shared.u64 t, %1; cvt.u32.u64 %0, t; }" : "=r"(sbase) : "l"(fsm));
    float* Ks = fsm + FD_KS;
    float (*edge)[NN]   = (float(*)[NN])(fsm + FD_EDGE);
    float (*nf)[2 * CC] = (float(*)[2 * CC])(fsm + FD_NF);
    float (*hb)[2 * CC] = (float(*)[2 * CC])(fsm + FD_HB);
    const int qt = blockIdx.x, b = blockIdx.y;   // qt 0..15
    const int tid = threadIdx.x, w = tid >> 5, lane = tid & 31;

    // stage Ks (padded) via cp.async
    for (int idx = tid; idx < NN * 32; idx += 256) {
        int j = idx >> 5, c4 = (idx & 31) << 2;
        CPA16(sbase + (uint32_t)(j * KS_STR + c4) * 4u, (const void*)(K + (b * NN + j) * CC + c4));
    }
    CPA_COMMIT();

    const int qi = qt * 8 + w;
    const int row = b * NN + qi;
    float qreg[4];
    #pragma unroll
    for (int h = 0; h < HH; h++) qreg[h] = Q[row * CC + h * DKK + lane];
    CPA_WAIT0();
    __syncthreads();

    // ---- attention (8 warps, 1 row each) ----
    const float inv = 0.17677669529663687f;
    float acc[4] = {0.f, 0.f, 0.f, 0.f};
    #pragma unroll
    for (int h = 0; h < HH; h++) {
        float sc[4] = {0.f, 0.f, 0.f, 0.f};
        #pragma unroll
        for (int d4 = 0; d4 < 8; d4++) {
            float q0 = __shfl_sync(0xffffffffu, qreg[h], d4 * 4);
            float q1 = __shfl_sync(0xffffffffu, qreg[h], d4 * 4 + 1);
            float q2 = __shfl_sync(0xffffffffu, qreg[h], d4 * 4 + 2);
            float q3 = __shfl_sync(0xffffffffu, qreg[h], d4 * 4 + 3);
            #pragma unroll
            for (int kk = 0; kk < 4; kk++) {
                const float4 kv = *(const float4*)&Ks[(kk * 32 + lane) * KS_STR + h * DKK + d4 * 4];
                sc[kk] += q0 * kv.x + q1 * kv.y + q2 * kv.z + q3 * kv.w;
            }
        }
        #pragma unroll
        for (int kk = 0; kk < 4; kk++) sc[kk] *= inv;
        float mx = fmaxf(fmaxf(sc[0], sc[1]), fmaxf(sc[2], sc[3]));
        #pragma unroll
        for (int st = 16; st > 0; st >>= 1) mx = fmaxf(mx, __shfl_xor_sync(0xffffffffu, mx, st));
        float ex[4]; float sm = 0.f;
        #pragma unroll
        for (int kk = 0; kk < 4; kk++) { ex[kk] = expf(sc[kk] - mx); sm += ex[kk]; }
        #pragma unroll
        for (int st = 16; st > 0; st >>= 1) sm += __shfl_xor_sync(0xffffffffu, sm, st);
        float r = 1.0f / sm;
        #pragma unroll
        for (int kk = 0; kk < 4; kk++) acc[kk] += ex[kk] * r;
    }

    // ---- edge + nf left half ----
    {
        float e[4];
        float ssum = 0.f;
        #pragma unroll
        for (int kk = 0; kk < 4; kk++) {
            int j = kk * 32 + lane;
            float v = ep[row * NN + j] * (acc[kk] * 0.25f);
            if (j == qi) v = 0.f;
            e[kk] = v;
            ssum += fabsf(v);
        }
        #pragma unroll
        for (int st = 16; st > 0; st >>= 1) ssum += __shfl_xor_sync(0xffffffffu, ssum, st);
        float rinv = 1.0f / fmaxf(ssum, 1e-12f);
        #pragma unroll
        for (int kk = 0; kk < 4; kk++) {
            int j = kk * 32 + lane;
            edge[w][j] = e[kk] * rinv;
            nf[w][j] = vp[row * CC + j];
        }
    }
    __syncthreads();   // Ks reads done -> wbufs usable

    const int c = tid & 127, rr = tid >> 7;   // rows rr + 2q

    // ---- aggr: 4 chunks of 32 j-rows ----
    {
        const float4* vsrc = (const float4*)(vp + b * NN * CC);
        ISSUE_CH(0, vsrc, 0);
        ISSUE_CH(1, vsrc, 1);
        float a[4] = {0.f, 0.f, 0.f, 0.f};
        for (int jc = 0; jc < 4; jc++) {
            if (jc + 2 < 4) { ISSUE_CH((jc + 2) & 3, vsrc, jc + 2); CPA_WAIT2(); }
            else if (jc + 1 < 4) { CPA_WAIT1(); }
            else { CPA_WAIT0(); }
            __syncthreads();
            const float* cur = fsm + (jc & 3) * 4096;
            #pragma unroll
            for (int jq = 0; jq < 8; jq++) {
                float v0 = cur[(jq * 4 + 0) * 128 + c];
                float v1 = cur[(jq * 4 + 1) * 128 + c];
                float v2 = cur[(jq * 4 + 2) * 128 + c];
                float v3 = cur[(jq * 4 + 3) * 128 + c];
                int j = jc * 32 + jq * 4;
                #pragma unroll
                for (int q = 0; q < 4; q++) {
                    const float4 e4 = *(const float4*)&edge[rr + 2 * q][j];
                    a[q] += e4.x * v0 + e4.y * v1 + e4.z * v2 + e4.w * v3;
                }
            }
        }
        #pragma unroll
        for (int q = 0; q < 4; q++) nf[rr + 2 * q][CC + c] = a[q];
    }

    // ---- layer1: 16 chunks of 16 k-rows of w1 [256k x 256o] ----
    {
        const float4* w1v = (const float4*)w1;
        ISSUE_CH(0, w1v, 0);
        ISSUE_CH(1, w1v, 1);
        float accm[8] = {0.f};
        for (int ch = 0; ch < 16; ch++) {
            if (ch + 2 < 16) { ISSUE_CH((ch + 2) & 3, w1v, ch + 2); CPA_WAIT2(); }
            else if (ch + 1 < 16) { CPA_WAIT1(); }
            else { CPA_WAIT0(); }
            __syncthreads();   // first iter: also publishes nf writes
            const float* cur = fsm + (ch & 3) * 4096;
            #pragma unroll
            for (int kq = 0; kq < 4; kq++) {
                float wv0 = cur[(kq * 4 + 0) * 256 + tid];
                float wv1 = cur[(kq * 4 + 1) * 256 + tid];
                float wv2 = cur[(kq * 4 + 2) * 256 + tid];
                float wv3 = cur[(kq * 4 + 3) * 256 + tid];
                int kb = ch * 16 + kq * 4;
                #pragma unroll
                for (int r = 0; r < 8; r++) {
                    const float4 aN = *(const float4*)&nf[r][kb];
                    accm[r] += aN.x * wv0 + aN.y * wv1 + aN.z * wv2 + aN.w * wv3;
                }
            }
        }
        #pragma unroll
        for (int r = 0; r < 8; r++) hb[r][tid] = lrelu(accm[r] * BN_SCALE);
    }

    // ---- layer2: 8 chunks of 32 k-rows of w2 [256k x 128o] ----
    {
        const float4* w2v = (const float4*)w2;
        ISSUE_CH(0, w2v, 0);
        ISSUE_CH(1, w2v, 1);
        float a[4] = {0.f, 0.f, 0.f, 0.f};
        for (int ch = 0; ch < 8; ch++) {
            if (ch + 2 < 8) { ISSUE_CH((ch + 2) & 3, w2v, ch + 2); CPA_WAIT2(); }
            else if (ch + 1 < 8) { CPA_WAIT1(); }
            else { CPA_WAIT0(); }
            __syncthreads();   // first iter: also publishes hb writes
            const float* cur = fsm + (ch & 3) * 4096;
            #pragma unroll
            for (int kq = 0; kq < 8; kq++) {
                float wv0 = cur[(kq * 4 + 0) * 128 + c];
                float wv1 = cur[(kq * 4 + 1) * 128 + c];
                float wv2 = cur[(kq * 4 + 2) * 128 + c];
                float wv3 = cur[(kq * 4 + 3) * 128 + c];
                int kb = ch * 32 + kq * 4;
                #pragma unroll
                for (int q = 0; q < 4; q++) {
                    const float4 h4 = *(const float4*)&hb[rr + 2 * q][kb];
                    a[q] += h4.x * wv0 + h4.y * wv1 + h4.z * wv2 + h4.w * wv3;
                }
            }
        }
        #pragma unroll
        for (int q = 0; q < 4; q++)
            vp_out[(b * NN + qt * 8 + rr + 2 * q) * CC + c] = lrelu(a[q] * BN_SCALE);
    }
}

// ---------------------------------------------------------------------------

extern "C" void kernel_launch(void* const* d_in, const int* in_sizes, int n_in,
                              void* d_out, int out_size)
{
    const float* vp   = (const float*)d_in[0];
    const float* ep0  = (const float*)d_in[1];
    const float* pw1  = (const float*)d_in[2];
    const float* pw2  = (const float*)d_in[3];
    const float* pw3  = (const float*)d_in[4];
    const float* pb3  = (const float*)d_in[5];
    const float* psw1 = (const float*)d_in[6];
    const float* psw2 = (const float*)d_in[7];
    const float* psw3 = (const float*)d_in[8];
    const float* psb3 = (const float*)d_in[9];
    const float* dw1  = (const float*)d_in[10];
    const float* dw2  = (const float*)d_in[11];
    const float* wq   = (const float*)d_in[12];
    const float* wk   = (const float*)d_in[13];
    float* out = (float*)d_out;

    cudaFuncSetAttribute(psim_mma, cudaFuncAttributeMaxDynamicSharedMemorySize, SMEM_PS);
    cudaFuncSetAttribute(mha_d2p_kernel, cudaFuncAttributeMaxDynamicSharedMemorySize, SMEM_FD);

    float *ep, *Q, *K, *vp1, *vp2;
    uint4 *w1P, *w2P;
    cudaGetSymbolAddress((void**)&ep, g_ep);
    cudaGetSymbolAddress((void**)&Q, g_Q);
    cudaGetSymbolAddress((void**)&K, g_K);
    cudaGetSymbolAddress((void**)&vp1, g_vp1);
    cudaGetSymbolAddress((void**)&vp2, g_vp2);
    cudaGetSymbolAddress((void**)&w1P, g_w1P);
    cudaGetSymbolAddress((void**)&w2P, g_w2P);

    prep_weights_all<<<dim3(16, 3), 256>>>(pw1, pw2, psw1, psw2, w1P, w2P);

    dim3 grid(NN, BB);
    dim3 grid8(16, BB);

    psim_mma<<<grid, 256, SMEM_PS>>>(vp, ep0, ep, w1P, w2P, pw3, pb3, 0);

    for (int g = 0; g < 2; g++) {
        const float* vpc = (g == 0) ? vp : vp1;
        float* vpn = (g == 0) ? vp1 : vp2;

        qk_kernel<<<grid8, 256>>>(vpc, wq + g * CC * CC, wk + g * CC * CC, Q, K);
        mha_d2p_kernel<<<grid8, 256, SMEM_FD>>>(Q, K, ep, vpc,
                                                dw1 + g * 2 * CC * 2 * CC,
                                                dw2 + g * 2 * CC * CC, vpn);

        const int kv = (g == 0) ? 115 : 102;
        float* epo = (g == 1) ? out : ep;
        psim_mma<<<grid, 256, SMEM_PS>>>(vpn, ep, epo,
                                         w1P + (g + 1) * 4096,
                                         w2P + (g + 1) * 4096,
                                         psw3 + g * CC,
                                         psb3 + g, kv);
    }
}

// round 16
// speedup vs baseline: 1.1642x; 1.0371x over previous
#include <cuda_runtime.h>
#include <math.h>
#include <stdint.h>

#define BB 8
#define NN 128
#define CC 128
#define C2 256
#define HH 4
#define DKK 32
#define BN_SCALE 0.9999950000374997f

__device__ float g_ep[BB*NN*NN];
__device__ float g_Q[BB*NN*CC];
__device__ float g_K[BB*NN*CC];
__device__ float g_vp1[BB*NN*CC];
__device__ float g_vp2[BB*NN*CC];
__device__ uint4 g_w1P[3 * 4096];
__device__ uint4 g_w2P[3 * 4096];

__device__ __forceinline__ float lrelu(float x) { return x > 0.f ? x : 0.01f * x; }
__device__ __forceinline__ uint32_t pack_bf16(float lo, float hi) {
    uint32_t r; asm("cvt.rn.bf16x2.f32 %0, %1, %2;" : "=r"(r) : "f"(hi), "f"(lo)); return r;
}

__device__ __forceinline__ void mma_bf16(float* c, const uint4& a, uint32_t b0, uint32_t b1) {
    asm volatile(
        "mma.sync.aligned.m16n8k16.row.col.f32.bf16.bf16.f32 "
        "{%0,%1,%2,%3}, {%4,%5,%6,%7}, {%8,%9}, {%0,%1,%2,%3};"
        : "+f"(c[0]), "+f"(c[1]), "+f"(c[2]), "+f"(c[3])
        : "r"(a.x), "r"(a.y), "r"(a.z), "r"(a.w), "r"(b0), "r"(b1));
}

// ---- cp.async helpers ----
#define CPA16(dst_smem, gptr) \
    asm volatile("cp.async.cg.shared.global [%0], [%1], 16;" :: "r"(dst_smem), "l"(gptr) : "memory")
#define CPA_COMMIT() asm volatile("cp.async.commit_group;" ::: "memory")
#define CPA_WAIT0()  asm volatile("cp.async.wait_group 0;" ::: "memory")
#define CPA_WAIT1()  asm volatile("cp.async.wait_group 1;" ::: "memory")
#define CPA_WAIT2()  asm volatile("cp.async.wait_group 2;" ::: "memory")

// ---------------- weight prep ------------------------------------------------
__global__ void prep_weights_all(const float* __restrict__ pw1, const float* __restrict__ pw2,
                                 const float* __restrict__ psw1, const float* __restrict__ psw2,
                                 uint4* __restrict__ w1P, uint4* __restrict__ w2P)
{
    const int set = blockIdx.y;
    const float* w1 = (set == 0) ? pw1 : psw1 + (set - 1) * CC * C2;
    const float* w2 = (set == 0) ? pw2 : psw2 + (set - 1) * C2 * CC;
    uint4* o1 = w1P + set * 4096;
    uint4* o2 = w2P + set * 4096;
    int idx = blockIdx.x * 256 + threadIdx.x;
    {
        int lane = idx & 31, kt = (idx >> 5) & 7, np = (idx >> 8) & 1, ch = idx >> 9;
        int o0 = ch * 32 + np * 16 + (lane >> 2);
        int k0 = kt * 16 + (lane & 3) * 2;
        uint4 v;
        v.x = pack_bf16(w1[k0 * C2 + o0],       w1[(k0 + 1) * C2 + o0]);
        v.y = pack_bf16(w1[(k0 + 8) * C2 + o0], w1[(k0 + 9) * C2 + o0]);
        v.z = pack_bf16(w1[k0 * C2 + o0 + 8],       w1[(k0 + 1) * C2 + o0 + 8]);
        v.w = pack_bf16(w1[(k0 + 8) * C2 + o0 + 8], w1[(k0 + 9) * C2 + o0 + 8]);
        o1[idx] = v;
    }
    {
        int lane = idx & 31, ktl = (idx >> 5) & 7, ntp = (idx >> 8) & 7, kh = idx >> 11;
        int o0 = ntp * 16 + (lane >> 2);
        int k0 = (kh * 8 + ktl) * 16 + (lane & 3) * 2;
        uint4 v;
        v.x = pack_bf16(w2[k0 * CC + o0],       w2[(k0 + 1) * CC + o0]);
        v.y = pack_bf16(w2[(k0 + 8) * CC + o0], w2[(k0 + 9) * CC + o0]);
        v.z = pack_bf16(w2[k0 * CC + o0 + 8],       w2[(k0 + 1) * CC + o0 + 8]);
        v.w = pack_bf16(w2[(k0 + 8) * CC + o0 + 8], w2[(k0 + 9) * CC + o0 + 8]);
        o2[idx] = v;
    }
}

// ---------------- psim via bf16 mma.sync + cp.async pipelines ----------------
#define MS_SIM  0
#define MS_H1   32768
#define MS_VPI  98304
#define MS_W3S  98816
#define MS_EPL  99328
#define MS_EROW 99840
#define MS_RED  100352
#define MS_L3   100864
#define SMEM_PS 101888

__global__ void __launch_bounds__(256, 2)
psim_mma(const float* __restrict__ vp,
         const float* __restrict__ ep_in,
         float* __restrict__ ep_out,
         const uint4* __restrict__ w1P,
         const uint4* __restrict__ w2P,
         const float* __restrict__ w3,
         const float* __restrict__ b3,
         int kval)
{
    extern __shared__ char smem[];
    uint32_t sbase;
    asm("{ .reg .u64 t; cvta.to.shared.u64 t, %1; cvt.u32.u64 %0, t; }" : "=r"(sbase) : "l"(smem));
    float* s_vpi  = (float*)(smem + MS_VPI);
    float* s_w3   = (float*)(smem + MS_W3S);
    float* s_epl  = (float*)(smem + MS_EPL);
    float* s_erow = (float*)(smem + MS_EROW);
    float* s_red  = (float*)(smem + MS_RED);
    float* s_l3   = (float*)(smem + MS_L3);
    const int i = blockIdx.x, b = blockIdx.y;
    const int tid = threadIdx.x, w = tid >> 5, lane = tid & 31;
    const int wm = w & 3, wn = w >> 2;
    const int row = b * NN + i;

    if (tid < 128) {
        s_vpi[tid] = vp[row * CC + tid];
        s_w3[tid]  = w3[tid];
        float v = ep_in[row * NN + tid];
        s_epl[tid] = (tid == i) ? 0.f : v;
    }
    __syncthreads();

    // build sim A-frags (bf16)
    for (int q = tid; q < 4096; q += 256) {
        int j = q >> 5, c0 = (q & 31) << 2;
        const float4 vj = *(const float4*)(vp + (b * NN + j) * CC + c0);
        const float4 vi = *(const float4*)(s_vpi + c0);
        float d0 = vi.x - vj.x, d1 = vi.y - vj.y, d2 = vi.z - vj.z, d3 = vi.w - vj.w;
        uint32_t p01 = pack_bf16(d0 * d0, d1 * d1);
        uint32_t p23 = pack_bf16(d2 * d2, d3 * d3);
        int kt = c0 >> 4, mt = j >> 4;
        uint32_t addr = (uint32_t)(((kt * 8 + mt) * 32 + (j & 7) * 4 + ((c0 & 7) >> 1)) * 16
                       + (((j >> 3) & 1) + (((c0 & 15) >> 3) << 1)) * 4);
        *(uint32_t*)(smem + MS_SIM + addr)      = p01;
        *(uint32_t*)(smem + MS_SIM + addr + 16) = p23;
    }
    __syncthreads();

    uint4 Areg[8][2];
    #pragma unroll
    for (int kt = 0; kt < 8; kt++)
        #pragma unroll
        for (int m = 0; m < 2; m++)
            Areg[kt][m] = *(const uint4*)(smem + MS_SIM + ((kt * 8 + wm * 2 + m) * 32 + lane) * 16);
    __syncthreads();   // all warps done reading sim; MS_SIM becomes staging ring

    // ---- GEMM1: w1 staged via cp.async, 4x8KB ring, depth 3 ----
    // chunk ch (8KB = 512 uint4): global w1P + ch*512; thread stages tid, tid+256
    #define PS_ISSUE_W1(ch) { \
        uint32_t _d = sbase + MS_SIM + (uint32_t)((ch) & 3) * 8192u + (uint32_t)tid * 16u; \
        const uint4* _g = w1P + (ch) * 512 + tid; \
        CPA16(_d, (const void*)_g); \
        CPA16(_d + 4096u, (const void*)(_g + 256)); \
        CPA_COMMIT(); }

    PS_ISSUE_W1(0); PS_ISSUE_W1(1); PS_ISSUE_W1(2);

    for (int ch = 0; ch < 8; ch++) {
        if (ch <= 5) { CPA_WAIT2(); }
        else if (ch == 6) { CPA_WAIT1(); }
        else { CPA_WAIT0(); }
        __syncthreads();
        if (ch + 3 < 8) PS_ISSUE_W1(ch + 3);

        const char* buf = smem + MS_SIM + (ch & 3) * 8192;
        float acc[2][2][4];
        #pragma unroll
        for (int m = 0; m < 2; m++)
            #pragma unroll
            for (int n = 0; n < 2; n++)
                #pragma unroll
                for (int t = 0; t < 4; t++) acc[m][n][t] = 0.f;
        #pragma unroll
        for (int kt = 0; kt < 8; kt++) {
            uint4 W = *(const uint4*)(buf + ((wn * 8 + kt) * 32 + lane) * 16);
            mma_bf16(acc[0][0], Areg[kt][0], W.x, W.y);
            mma_bf16(acc[0][1], Areg[kt][0], W.z, W.w);
            mma_bf16(acc[1][0], Areg[kt][1], W.x, W.y);
            mma_bf16(acc[1][1], Areg[kt][1], W.z, W.w);
        }
        #pragma unroll
        for (int m = 0; m < 2; m++)
            #pragma unroll
            for (int ntl = 0; ntl < 2; ntl++) {
                uint2 st;
                st.x = pack_bf16(lrelu(acc[m][ntl][0] * BN_SCALE), lrelu(acc[m][ntl][1] * BN_SCALE));
                st.y = pack_bf16(lrelu(acc[m][ntl][2] * BN_SCALE), lrelu(acc[m][ntl][3] * BN_SCALE));
                uint32_t addr = (uint32_t)((((ch * 2 + wn) * 8 + wm * 2 + m) * 32 + lane) * 16 + ntl * 8);
                *(uint2*)(smem + MS_H1 + addr) = st;
            }
    }
    __syncthreads();   // GEMM1 done: h1 visible, staging ring free

    // ---- GEMM2: w2P staged via cp.async, 2x16KB ping-pong, depth 1 ----
    // chunk ci = (kh = ci>>1, ktlh = ci&1), 16KB = 1024 uint4
    // staged layout: [ntp(8)][ktll(4)][lane(32)]
    #define PS_ISSUE_W2(ci) { \
        uint32_t _d = sbase + MS_SIM + (uint32_t)((ci) & 1) * 16384u; \
        int _kh = (ci) >> 1, _ktlh = (ci) & 1; \
        _Pragma("unroll") \
        for (int _t = 0; _t < 4; _t++) { \
            int _s = tid + _t * 256; \
            int _ntp = _s >> 7, _ktll = (_s >> 5) & 3, _ln = _s & 31; \
            const uint4* _g = w2P + _kh * 2048 + _ntp * 256 + (_ktlh * 4 + _ktll) * 32 + _ln; \
            CPA16(_d + (uint32_t)_s * 16u, (const void*)_g); \
        } \
        CPA_COMMIT(); }

    float acc2[2][8][4];
    #pragma unroll
    for (int m = 0; m < 2; m++)
        #pragma unroll
        for (int n = 0; n < 8; n++)
            #pragma unroll
            for (int t = 0; t < 4; t++) acc2[m][n][t] = 0.f;

    PS_ISSUE_W2(0); PS_ISSUE_W2(1);

    for (int ci = 0; ci < 4; ci++) {
        if (ci < 3) { CPA_WAIT1(); } else { CPA_WAIT0(); }
        __syncthreads();
        const char* buf = smem + MS_SIM + (ci & 1) * 16384;
        const int ktbase = (ci >> 1) * 8 + (ci & 1) * 4;
        #pragma unroll
        for (int ktll = 0; ktll < 4; ktll++) {
            int kt2 = ktbase + ktll;
            uint4 A0 = *(const uint4*)(smem + MS_H1 + ((kt2 * 8 + wm * 2) * 32 + lane) * 16);
            uint4 A1 = *(const uint4*)(smem + MS_H1 + ((kt2 * 8 + wm * 2 + 1) * 32 + lane) * 16);
            #pragma unroll
            for (int pp = 0; pp < 4; pp++) {
                uint4 W = *(const uint4*)(buf + (((wn * 4 + pp) * 4 + ktll) * 32 + lane) * 16);
                int q = pp * 2;
                mma_bf16(acc2[0][q],     A0, W.x, W.y);
                mma_bf16(acc2[0][q + 1], A0, W.z, W.w);
                mma_bf16(acc2[1][q],     A1, W.x, W.y);
                mma_bf16(acc2[1][q + 1], A1, W.z, W.w);
            }
        }
        __syncthreads();
        if (ci + 2 < 4) PS_ISSUE_W2(ci + 2);
    }

    // ---- layer3 partials + reduce ----
    const float b3v = b3[0];
    float pr[4] = {0.f, 0.f, 0.f, 0.f};
    #pragma unroll
    for (int m = 0; m < 2; m++)
        #pragma unroll
        for (int q = 0; q < 8; q++) {
            int o = wn * 64 + q * 8 + (lane & 3) * 2;
            float wa = s_w3[o], wb = s_w3[o + 1];
            pr[m * 2]     += lrelu(acc2[m][q][0] * BN_SCALE) * wa + lrelu(acc2[m][q][1] * BN_SCALE) * wb;
            pr[m * 2 + 1] += lrelu(acc2[m][q][2] * BN_SCALE) * wa + lrelu(acc2[m][q][3] * BN_SCALE) * wb;
        }
    #pragma unroll
    for (int t = 0; t < 4; t++) {
        pr[t] += __shfl_xor_sync(0xffffffffu, pr[t], 1);
        pr[t] += __shfl_xor_sync(0xffffffffu, pr[t], 2);
    }
    if ((lane & 3) == 0) {
        int g = lane >> 2;
        s_l3[wn * 128 + wm * 32 + g]      = pr[0];
        s_l3[wn * 128 + wm * 32 + g + 8]  = pr[1];
        s_l3[wn * 128 + wm * 32 + g + 16] = pr[2];
        s_l3[wn * 128 + wm * 32 + g + 24] = pr[3];
    }
    __syncthreads();
    if (tid < 128) {
        float e = s_l3[tid] + s_l3[128 + tid];
        s_erow[tid] = 1.0f / (1.0f + expf(-(e + b3v)));
    }
    __syncthreads();

    // ---- row postprocess (warp-shuffle reductions) ----
    if (tid < 128) s_erow[tid] *= s_epl[tid];
    __syncthreads();

    if (w == 0) {
        float v = s_epl[lane] + s_epl[lane + 32] + s_epl[lane + 64] + s_epl[lane + 96];
        #pragma unroll
        for (int st = 16; st > 0; st >>= 1) v += __shfl_xor_sync(0xffffffffu, v, st);
        if (lane == 0) s_red[0] = v;
    }
    int cnt = 0;
    if (kval > 0 && tid < 128) {
        float mine = s_erow[tid];
        for (int jj = 0; jj < NN; jj++) {
            float vv = s_erow[jj];
            cnt += (vv > mine) || (vv == mine && jj < tid);
        }
    }
    __syncthreads();
    if (kval > 0 && tid < 128 && cnt >= kval) s_erow[tid] = 0.f;
    __syncthreads();

    if (w == 0) {
        float v = fabsf(s_erow[lane]) + fabsf(s_erow[lane + 32])
                + fabsf(s_erow[lane + 64]) + fabsf(s_erow[lane + 96]);
        #pragma unroll
        for (int st = 16; st > 0; st >>= 1) v += __shfl_xor_sync(0xffffffffu, v, st);
        if (lane == 0) s_red[1] = v;
    }
    __syncthreads();

    const float scale = s_red[0] / fmaxf(s_red[1], 1e-12f);
    if (tid < 128)
        s_erow[tid] = s_erow[tid] * scale + ((tid == i) ? 1.0f : 0.0f) + 1e-6f;
    __syncthreads();

    if (w == 0) {
        float v = s_erow[lane] + s_erow[lane + 32] + s_erow[lane + 64] + s_erow[lane + 96];
        #pragma unroll
        for (int st = 16; st > 0; st >>= 1) v += __shfl_xor_sync(0xffffffffu, v, st);
        if (lane == 0) s_red[2] = v;
    }
    __syncthreads();

    if (tid < 128) ep_out[row * NN + tid] = s_erow[tid] / s_red[2];
}

// ---------------- Q/K projection: 8-row tiles --------------------------------
__global__ void __launch_bounds__(256)
qk_kernel(const float* __restrict__ vp,
          const float* __restrict__ wq,
          const float* __restrict__ wk,
          float* __restrict__ Q,
          float* __restrict__ K)
{
    __shared__ float vr[8][CC];
    const int rt = blockIdx.x, b = blockIdx.y;
    const int r0 = b * NN + rt * 8;
    const int tid = threadIdx.x;

    #pragma unroll
    for (int t = 0; t < 4; t++) {
        int idx = tid + t * 256;
        vr[idx >> 7][idx & 127] = vp[r0 * CC + idx];
    }
    __syncthreads();

    const float* wcol = ((tid < 128) ? wq : wk) + (tid & 127);
    float acc[8] = {0.f};
    #pragma unroll 8
    for (int c = 0; c < CC; c++) {
        float wv = __ldg(wcol + c * CC);
        #pragma unroll
        for (int r = 0; r < 8; r++) acc[r] += vr[r][c] * wv;
    }
    float* dst = (tid < 128) ? Q : K;
    #pragma unroll
    for (int r = 0; r < 8; r++) dst[(r0 + r) * CC + (tid & 127)] = acc[r];
}

// ---------------- Fused MHA + D2P: cp.async 4-buffer pipelines ---------------
#define KS_STR 132
#define FD_KS    0
#define FD_EDGE  (NN * KS_STR)
#define FD_NF    (FD_EDGE + 8 * NN)
#define FD_HB    (FD_NF + 8 * 2 * CC)
#define SMEM_FD  ((FD_HB + 8 * 2 * CC) * 4)

#define ISSUE_CH(bufidx, srcf4, chn) { \
    const float4* _g = (srcf4) + (chn) * 1024 + tid; \
    uint32_t _d = sbase + (uint32_t)(bufidx) * 16384u + (uint32_t)tid * 16u; \
    CPA16(_d, (const void*)_g); \
    CPA16(_d + 4096u, (const void*)(_g + 256)); \
    CPA16(_d + 8192u, (const void*)(_g + 512)); \
    CPA16(_d + 12288u, (const void*)(_g + 768)); \
    CPA_COMMIT(); }

__global__ void __launch_bounds__(256)
mha_d2p_kernel(const float* __restrict__ Q,
               const float* __restrict__ K,
               const float* __restrict__ ep,
               const float* __restrict__ vp,
               const float* __restrict__ w1,
               const float* __restrict__ w2,
               float* __restrict__ vp_out)
{
    extern __shared__ float fsm[];
    uint32_t sbase;
    asm("{ .reg .u64 t; cvta.to.shared.u64 t, %1; cvt.u32.u64 %0, t; }" : "=r"(sbase) : "l"(fsm));
    float* Ks = fsm + FD_KS;
    float (*edge)[NN]   = (float(*)[NN])(fsm + FD_EDGE);
    float (*nf)[2 * CC] = (float(*)[2 * CC])(fsm + FD_NF);
    float (*hb)[2 * CC] = (float(*)[2 * CC])(fsm + FD_HB);
    const int qt = blockIdx.x, b = blockIdx.y;
    const int tid = threadIdx.x, w = tid >> 5, lane = tid & 31;

    for (int idx = tid; idx < NN * 32; idx += 256) {
        int j = idx >> 5, c4 = (idx & 31) << 2;
        CPA16(sbase + (uint32_t)(j * KS_STR + c4) * 4u, (const void*)(K + (b * NN + j) * CC + c4));
    }
    CPA_COMMIT();

    const int qi = qt * 8 + w;
    const int row = b * NN + qi;
    float qreg[4];
    #pragma unroll
    for (int h = 0; h < HH; h++) qreg[h] = Q[row * CC + h * DKK + lane];
    CPA_WAIT0();
    __syncthreads();

    const float inv = 0.17677669529663687f;
    float acc[4] = {0.f, 0.f, 0.f, 0.f};
    #pragma unroll
    for (int h = 0; h < HH; h++) {
        float sc[4] = {0.f, 0.f, 0.f, 0.f};
        #pragma unroll
        for (int d4 = 0; d4 < 8; d4++) {
            float q0 = __shfl_sync(0xffffffffu, qreg[h], d4 * 4);
            float q1 = __shfl_sync(0xffffffffu, qreg[h], d4 * 4 + 1);
            float q2 = __shfl_sync(0xffffffffu, qreg[h], d4 * 4 + 2);
            float q3 = __shfl_sync(0xffffffffu, qreg[h], d4 * 4 + 3);
            #pragma unroll
            for (int kk = 0; kk < 4; kk++) {
                const float4 kv = *(const float4*)&Ks[(kk * 32 + lane) * KS_STR + h * DKK + d4 * 4];
                sc[kk] += q0 * kv.x + q1 * kv.y + q2 * kv.z + q3 * kv.w;
            }
        }
        #pragma unroll
        for (int kk = 0; kk < 4; kk++) sc[kk] *= inv;
        float mx = fmaxf(fmaxf(sc[0], sc[1]), fmaxf(sc[2], sc[3]));
        #pragma unroll
        for (int st = 16; st > 0; st >>= 1) mx = fmaxf(mx, __shfl_xor_sync(0xffffffffu, mx, st));
        float ex[4]; float sm = 0.f;
        #pragma unroll
        for (int kk = 0; kk < 4; kk++) { ex[kk] = expf(sc[kk] - mx); sm += ex[kk]; }
        #pragma unroll
        for (int st = 16; st > 0; st >>= 1) sm += __shfl_xor_sync(0xffffffffu, sm, st);
        float r = 1.0f / sm;
        #pragma unroll
        for (int kk = 0; kk < 4; kk++) acc[kk] += ex[kk] * r;
    }

    {
        float e[4];
        float ssum = 0.f;
        #pragma unroll
        for (int kk = 0; kk < 4; kk++) {
            int j = kk * 32 + lane;
            float v = ep[row * NN + j] * (acc[kk] * 0.25f);
            if (j == qi) v = 0.f;
            e[kk] = v;
            ssum += fabsf(v);
        }
        #pragma unroll
        for (int st = 16; st > 0; st >>= 1) ssum += __shfl_xor_sync(0xffffffffu, ssum, st);
        float rinv = 1.0f / fmaxf(ssum, 1e-12f);
        #pragma unroll
        for (int kk = 0; kk < 4; kk++) {
            int j = kk * 32 + lane;
            edge[w][j] = e[kk] * rinv;
            nf[w][j] = vp[row * CC + j];
        }
    }
    __syncthreads();

    const int c = tid & 127, rr = tid >> 7;

    {
        const float4* vsrc = (const float4*)(vp + b * NN * CC);
        ISSUE_CH(0, vsrc, 0);
        ISSUE_CH(1, vsrc, 1);
        float a[4] = {0.f, 0.f, 0.f, 0.f};
        for (int jc = 0; jc < 4; jc++) {
            if (jc + 2 < 4) { ISSUE_CH((jc + 2) & 3, vsrc, jc + 2); CPA_WAIT2(); }
            else if (jc + 1 < 4) { CPA_WAIT1(); }
            else { CPA_WAIT0(); }
            __syncthreads();
            const float* cur = fsm + (jc & 3) * 4096;
            #pragma unroll
            for (int jq = 0; jq < 8; jq++) {
                float v0 = cur[(jq * 4 + 0) * 128 + c];
                float v1 = cur[(jq * 4 + 1) * 128 + c];
                float v2 = cur[(jq * 4 + 2) * 128 + c];
                float v3 = cur[(jq * 4 + 3) * 128 + c];
                int j = jc * 32 + jq * 4;
                #pragma unroll
                for (int q = 0; q < 4; q++) {
                    const float4 e4 = *(const float4*)&edge[rr + 2 * q][j];
                    a[q] += e4.x * v0 + e4.y * v1 + e4.z * v2 + e4.w * v3;
                }
            }
        }
        #pragma unroll
        for (int q = 0; q < 4; q++) nf[rr + 2 * q][CC + c] = a[q];
    }

    {
        const float4* w1v = (const float4*)w1;
        ISSUE_CH(0, w1v, 0);
        ISSUE_CH(1, w1v, 1);
        float accm[8] = {0.f};
        for (int ch = 0; ch < 16; ch++) {
            if (ch + 2 < 16) { ISSUE_CH((ch + 2) & 3, w1v, ch + 2); CPA_WAIT2(); }
            else if (ch + 1 < 16) { CPA_WAIT1(); }
            else { CPA_WAIT0(); }
            __syncthreads();
            const float* cur = fsm + (ch & 3) * 4096;
            #pragma unroll
            for (int kq = 0; kq < 4; kq++) {
                float wv0 = cur[(kq * 4 + 0) * 256 + tid];
                float wv1 = cur[(kq * 4 + 1) * 256 + tid];
                float wv2 = cur[(kq * 4 + 2) * 256 + tid];
                float wv3 = cur[(kq * 4 + 3) * 256 + tid];
                int kb = ch * 16 + kq * 4;
                #pragma unroll
                for (int r = 0; r < 8; r++) {
                    const float4 aN = *(const float4*)&nf[r][kb];
                    accm[r] += aN.x * wv0 + aN.y * wv1 + aN.z * wv2 + aN.w * wv3;
                }
            }
        }
        #pragma unroll
        for (int r = 0; r < 8; r++) hb[r][tid] = lrelu(accm[r] * BN_SCALE);
    }

    {
        const float4* w2v = (const float4*)w2;
        ISSUE_CH(0, w2v, 0);
        ISSUE_CH(1, w2v, 1);
        float a[4] = {0.f, 0.f, 0.f, 0.f};
        for (int ch = 0; ch < 8; ch++) {
            if (ch + 2 < 8) { ISSUE_CH((ch + 2) & 3, w2v, ch + 2); CPA_WAIT2(); }
            else if (ch + 1 < 8) { CPA_WAIT1(); }
            else { CPA_WAIT0(); }
            __syncthreads();
            const float* cur = fsm + (ch & 3) * 4096;
            #pragma unroll
            for (int kq = 0; kq < 8; kq++) {
                float wv0 = cur[(kq * 4 + 0) * 128 + c];
                float wv1 = cur[(kq * 4 + 1) * 128 + c];
                float wv2 = cur[(kq * 4 + 2) * 128 + c];
                float wv3 = cur[(kq * 4 + 3) * 128 + c];
                int kb = ch * 32 + kq * 4;
                #pragma unroll
                for (int q = 0; q < 4; q++) {
                    const float4 h4 = *(const float4*)&hb[rr + 2 * q][kb];
                    a[q] += h4.x * wv0 + h4.y * wv1 + h4.z * wv2 + h4.w * wv3;
                }
            }
        }
        #pragma unroll
        for (int q = 0; q < 4; q++)
            vp_out[(b * NN + qt * 8 + rr + 2 * q) * CC + c] = lrelu(a[q] * BN_SCALE);
    }
}

// ---------------------------------------------------------------------------

extern "C" void kernel_launch(void* const* d_in, const int* in_sizes, int n_in,
                              void* d_out, int out_size)
{
    const float* vp   = (const float*)d_in[0];
    const float* ep0  = (const float*)d_in[1];
    const float* pw1  = (const float*)d_in[2];
    const float* pw2  = (const float*)d_in[3];
    const float* pw3  = (const float*)d_in[4];
    const float* pb3  = (const float*)d_in[5];
    const float* psw1 = (const float*)d_in[6];
    const float* psw2 = (const float*)d_in[7];
    const float* psw3 = (const float*)d_in[8];
    const float* psb3 = (const float*)d_in[9];
    const float* dw1  = (const float*)d_in[10];
    const float* dw2  = (const float*)d_in[11];
    const float* wq   = (const float*)d_in[12];
    const float* wk   = (const float*)d_in[13];
    float* out = (float*)d_out;

    cudaFuncSetAttribute(psim_mma, cudaFuncAttributeMaxDynamicSharedMemorySize, SMEM_PS);
    cudaFuncSetAttribute(mha_d2p_kernel, cudaFuncAttributeMaxDynamicSharedMemorySize, SMEM_FD);

    float *ep, *Q, *K, *vp1, *vp2;
    uint4 *w1P, *w2P;
    cudaGetSymbolAddress((void**)&ep, g_ep);
    cudaGetSymbolAddress((void**)&Q, g_Q);
    cudaGetSymbolAddress((void**)&K, g_K);
    cudaGetSymbolAddress((void**)&vp1, g_vp1);
    cudaGetSymbolAddress((void**)&vp2, g_vp2);
    cudaGetSymbolAddress((void**)&w1P, g_w1P);
    cudaGetSymbolAddress((void**)&w2P, g_w2P);

    prep_weights_all<<<dim3(16, 3), 256>>>(pw1, pw2, psw1, psw2, w1P, w2P);

    dim3 grid(NN, BB);
    dim3 grid8(16, BB);

    psim_mma<<<grid, 256, SMEM_PS>>>(vp, ep0, ep, w1P, w2P, pw3, pb3, 0);

    for (int g = 0; g < 2; g++) {
        const float* vpc = (g == 0) ? vp : vp1;
        float* vpn = (g == 0) ? vp1 : vp2;

        qk_kernel<<<grid8, 256>>>(vpc, wq + g * CC * CC, wk + g * CC * CC, Q, K);
        mha_d2p_kernel<<<grid8, 256, SMEM_FD>>>(Q, K, ep, vpc,
                                                dw1 + g * 2 * CC * 2 * CC,
                                                dw2 + g * 2 * CC * CC, vpn);

        const int kv = (g == 0) ? 115 : 102;
        float* epo = (g == 1) ? out : ep;
        psim_mma<<<grid, 256, SMEM_PS>>>(vpn, ep, epo,
                                         w1P + (g + 1) * 4096,
                                         w2P + (g + 1) * 4096,
                                         psw3 + g * CC,
                                         psb3 + g, kv);
    }
}

// round 17
// speedup vs baseline: 1.1735x; 1.0079x over previous
#include <cuda_runtime.h>
#include <math.h>
#include <stdint.h>

#define BB 8
#define NN 128
#define CC 128
#define C2 256
#define HH 4
#define DKK 32
#define BN_SCALE 0.9999950000374997f

__device__ float g_ep[BB*NN*NN];
__device__ float g_Q[BB*NN*CC];
__device__ float g_K[BB*NN*CC];
__device__ float g_vp1[BB*NN*CC];
__device__ float g_vp2[BB*NN*CC];
__device__ uint4 g_w1P[3 * 4096];
__device__ uint4 g_w2P[3 * 4096];

__device__ __forceinline__ float lrelu(float x) { return x > 0.f ? x : 0.01f * x; }
__device__ __forceinline__ uint32_t pack_bf16(float lo, float hi) {
    uint32_t r; asm("cvt.rn.bf16x2.f32 %0, %1, %2;" : "=r"(r) : "f"(hi), "f"(lo)); return r;
}

__device__ __forceinline__ void mma_bf16(float* c, const uint4& a, uint32_t b0, uint32_t b1) {
    asm volatile(
        "mma.sync.aligned.m16n8k16.row.col.f32.bf16.bf16.f32 "
        "{%0,%1,%2,%3}, {%4,%5,%6,%7}, {%8,%9}, {%0,%1,%2,%3};"
        : "+f"(c[0]), "+f"(c[1]), "+f"(c[2]), "+f"(c[3])
        : "r"(a.x), "r"(a.y), "r"(a.z), "r"(a.w), "r"(b0), "r"(b1));
}

// ---- cp.async helpers ----
#define CPA16(dst_smem, gptr) \
    asm volatile("cp.async.cg.shared.global [%0], [%1], 16;" :: "r"(dst_smem), "l"(gptr) : "memory")
#define CPA_COMMIT() asm volatile("cp.async.commit_group;" ::: "memory")
#define CPA_WAIT0()  asm volatile("cp.async.wait_group 0;" ::: "memory")
#define CPA_WAIT1()  asm volatile("cp.async.wait_group 1;" ::: "memory")
#define CPA_WAIT2()  asm volatile("cp.async.wait_group 2;" ::: "memory")

// ---------------- weight prep ------------------------------------------------
__global__ void prep_weights_all(const float* __restrict__ pw1, const float* __restrict__ pw2,
                                 const float* __restrict__ psw1, const float* __restrict__ psw2,
                                 uint4* __restrict__ w1P, uint4* __restrict__ w2P)
{
    const int set = blockIdx.y;
    const float* w1 = (set == 0) ? pw1 : psw1 + (set - 1) * CC * C2;
    const float* w2 = (set == 0) ? pw2 : psw2 + (set - 1) * C2 * CC;
    uint4* o1 = w1P + set * 4096;
    uint4* o2 = w2P + set * 4096;
    int idx = blockIdx.x * 256 + threadIdx.x;
    {
        int lane = idx & 31, kt = (idx >> 5) & 7, np = (idx >> 8) & 1, ch = idx >> 9;
        int o0 = ch * 32 + np * 16 + (lane >> 2);
        int k0 = kt * 16 + (lane & 3) * 2;
        uint4 v;
        v.x = pack_bf16(w1[k0 * C2 + o0],       w1[(k0 + 1) * C2 + o0]);
        v.y = pack_bf16(w1[(k0 + 8) * C2 + o0], w1[(k0 + 9) * C2 + o0]);
        v.z = pack_bf16(w1[k0 * C2 + o0 + 8],       w1[(k0 + 1) * C2 + o0 + 8]);
        v.w = pack_bf16(w1[(k0 + 8) * C2 + o0 + 8], w1[(k0 + 9) * C2 + o0 + 8]);
        o1[idx] = v;
    }
    {
        int lane = idx & 31, ktl = (idx >> 5) & 7, ntp = (idx >> 8) & 7, kh = idx >> 11;
        int o0 = ntp * 16 + (lane >> 2);
        int k0 = (kh * 8 + ktl) * 16 + (lane & 3) * 2;
        uint4 v;
        v.x = pack_bf16(w2[k0 * CC + o0],       w2[(k0 + 1) * CC + o0]);
        v.y = pack_bf16(w2[(k0 + 8) * CC + o0], w2[(k0 + 9) * CC + o0]);
        v.z = pack_bf16(w2[k0 * CC + o0 + 8],       w2[(k0 + 1) * CC + o0 + 8]);
        v.w = pack_bf16(w2[(k0 + 8) * CC + o0 + 8], w2[(k0 + 9) * CC + o0 + 8]);
        o2[idx] = v;
    }
}

// ---------------- psim via bf16 mma.sync + cp.async pipelines ----------------
#define MS_SIM  0
#define MS_H1   32768
#define MS_VPI  98304
#define MS_W3S  98816
#define MS_EPL  99328
#define MS_EROW 99840
#define MS_RED  100352
#define MS_L3   100864
#define MS_EXT  101888      // dedicated 8KB staging buffer (GEMM1 ring slot 0)
#define SMEM_PS 110080

__global__ void __launch_bounds__(256, 2)
psim_mma(const float* __restrict__ vp,
         const float* __restrict__ ep_in,
         float* __restrict__ ep_out,
         const uint4* __restrict__ w1P,
         const uint4* __restrict__ w2P,
         const float* __restrict__ w3,
         const float* __restrict__ b3,
         int kval)
{
    extern __shared__ char smem[];
    uint32_t sbase;
    asm("{ .reg .u64 t; cvta.to.shared.u64 t, %1; cvt.u32.u64 %0, t; }" : "=r"(sbase) : "l"(smem));
    float* s_vpi  = (float*)(smem + MS_VPI);
    float* s_w3   = (float*)(smem + MS_W3S);
    float* s_epl  = (float*)(smem + MS_EPL);
    float* s_erow = (float*)(smem + MS_EROW);
    float* s_red  = (float*)(smem + MS_RED);
    float* s_l3   = (float*)(smem + MS_L3);
    const int i = blockIdx.x, b = blockIdx.y;
    const int tid = threadIdx.x, w = tid >> 5, lane = tid & 31;
    const int wm = w & 3, wn = w >> 2;
    const int row = b * NN + i;

    // GEMM1 ring: slot 0 -> MS_EXT, slots 1..3 -> MS_SIM + s*8192
    #define PS_SLOT(s) ((s) == 0 ? (uint32_t)MS_EXT : (uint32_t)MS_SIM + (uint32_t)(s) * 8192u)
    #define PS_ISSUE_W1(ch) { \
        uint32_t _d = sbase + PS_SLOT((ch) & 3) + (uint32_t)tid * 16u; \
        const uint4* _g = w1P + (ch) * 512 + tid; \
        CPA16(_d, (const void*)_g); \
        CPA16(_d + 4096u, (const void*)(_g + 256)); \
        CPA_COMMIT(); }

    // pre-issue GEMM1 chunk 0 into the dedicated buffer (hides under sim build)
    PS_ISSUE_W1(0);

    if (tid < 128) {
        s_vpi[tid] = vp[row * CC + tid];
        s_w3[tid]  = w3[tid];
        float v = ep_in[row * NN + tid];
        s_epl[tid] = (tid == i) ? 0.f : v;
    }
    __syncthreads();

    // build sim A-frags (bf16)
    for (int q = tid; q < 4096; q += 256) {
        int j = q >> 5, c0 = (q & 31) << 2;
        const float4 vj = *(const float4*)(vp + (b * NN + j) * CC + c0);
        const float4 vi = *(const float4*)(s_vpi + c0);
        float d0 = vi.x - vj.x, d1 = vi.y - vj.y, d2 = vi.z - vj.z, d3 = vi.w - vj.w;
        uint32_t p01 = pack_bf16(d0 * d0, d1 * d1);
        uint32_t p23 = pack_bf16(d2 * d2, d3 * d3);
        int kt = c0 >> 4, mt = j >> 4;
        uint32_t addr = (uint32_t)(((kt * 8 + mt) * 32 + (j & 7) * 4 + ((c0 & 7) >> 1)) * 16
                       + (((j >> 3) & 1) + (((c0 & 15) >> 3) << 1)) * 4);
        *(uint32_t*)(smem + MS_SIM + addr)      = p01;
        *(uint32_t*)(smem + MS_SIM + addr + 16) = p23;
    }
    __syncthreads();

    uint4 Areg[8][2];
    #pragma unroll
    for (int kt = 0; kt < 8; kt++)
        #pragma unroll
        for (int m = 0; m < 2; m++)
            Areg[kt][m] = *(const uint4*)(smem + MS_SIM + ((kt * 8 + wm * 2 + m) * 32 + lane) * 16);
    __syncthreads();   // all warps done reading sim; MS_SIM slots 1..3 usable

    PS_ISSUE_W1(1); PS_ISSUE_W1(2);

    // GEMM2 chunk issue macro (2x16KB ping-pong at MS_SIM + {0,16384})
    #define PS_ISSUE_W2(ci) { \
        uint32_t _d = sbase + MS_SIM + (uint32_t)((ci) & 1) * 16384u; \
        int _kh = (ci) >> 1, _ktlh = (ci) & 1; \
        _Pragma("unroll") \
        for (int _t = 0; _t < 4; _t++) { \
            int _s = tid + _t * 256; \
            int _ntp = _s >> 7, _ktll = (_s >> 5) & 3, _ln = _s & 31; \
            const uint4* _g = w2P + _kh * 2048 + _ntp * 256 + (_ktlh * 4 + _ktll) * 32 + _ln; \
            CPA16(_d + (uint32_t)_s * 16u, (const void*)_g); \
        } \
        CPA_COMMIT(); }

    for (int ch = 0; ch < 8; ch++) {
        if (ch <= 5) { CPA_WAIT2(); }
        else { CPA_WAIT1(); }   // ch 6,7: allow the pre-issued W2(0) (and trailing w1) to pend
        __syncthreads();
        if (ch + 3 < 8) PS_ISSUE_W1(ch + 3);
        if (ch == 6) PS_ISSUE_W2(0);   // target MS_SIM+0..16KB: slot1 free (last read iter 5)

        const char* buf = smem + PS_SLOT(ch & 3);
        float acc[2][2][4];
        #pragma unroll
        for (int m = 0; m < 2; m++)
            #pragma unroll
            for (int n = 0; n < 2; n++)
                #pragma unroll
                for (int t = 0; t < 4; t++) acc[m][n][t] = 0.f;
        #pragma unroll
        for (int kt = 0; kt < 8; kt++) {
            uint4 W = *(const uint4*)(buf + ((wn * 8 + kt) * 32 + lane) * 16);
            mma_bf16(acc[0][0], Areg[kt][0], W.x, W.y);
            mma_bf16(acc[0][1], Areg[kt][0], W.z, W.w);
            mma_bf16(acc[1][0], Areg[kt][1], W.x, W.y);
            mma_bf16(acc[1][1], Areg[kt][1], W.z, W.w);
        }
        #pragma unroll
        for (int m = 0; m < 2; m++)
            #pragma unroll
            for (int ntl = 0; ntl < 2; ntl++) {
                uint2 st;
                st.x = pack_bf16(lrelu(acc[m][ntl][0] * BN_SCALE), lrelu(acc[m][ntl][1] * BN_SCALE));
                st.y = pack_bf16(lrelu(acc[m][ntl][2] * BN_SCALE), lrelu(acc[m][ntl][3] * BN_SCALE));
                uint32_t addr = (uint32_t)((((ch * 2 + wn) * 8 + wm * 2 + m) * 32 + lane) * 16 + ntl * 8);
                *(uint2*)(smem + MS_H1 + addr) = st;
            }
        if (ch < 7) __syncthreads();
    }
    __syncthreads();   // GEMM1 done: h1 visible; slots 2,3 (W2 buf1 region) free

    float acc2[2][8][4];
    #pragma unroll
    for (int m = 0; m < 2; m++)
        #pragma unroll
        for (int n = 0; n < 8; n++)
            #pragma unroll
            for (int t = 0; t < 4; t++) acc2[m][n][t] = 0.f;

    PS_ISSUE_W2(1);

    for (int ci = 0; ci < 4; ci++) {
        if (ci < 3) { CPA_WAIT1(); } else { CPA_WAIT0(); }
        __syncthreads();
        const char* buf = smem + MS_SIM + (ci & 1) * 16384;
        const int ktbase = (ci >> 1) * 8 + (ci & 1) * 4;
        #pragma unroll
        for (int ktll = 0; ktll < 4; ktll++) {
            int kt2 = ktbase + ktll;
            uint4 A0 = *(const uint4*)(smem + MS_H1 + ((kt2 * 8 + wm * 2) * 32 + lane) * 16);
            uint4 A1 = *(const uint4*)(smem + MS_H1 + ((kt2 * 8 + wm * 2 + 1) * 32 + lane) * 16);
            #pragma unroll
            for (int pp = 0; pp < 4; pp++) {
                uint4 W = *(const uint4*)(buf + (((wn * 4 + pp) * 4 + ktll) * 32 + lane) * 16);
                int q = pp * 2;
                mma_bf16(acc2[0][q],     A0, W.x, W.y);
                mma_bf16(acc2[0][q + 1], A0, W.z, W.w);
                mma_bf16(acc2[1][q],     A1, W.x, W.y);
                mma_bf16(acc2[1][q + 1], A1, W.z, W.w);
            }
        }
        __syncthreads();
        if (ci + 2 < 4) PS_ISSUE_W2(ci + 2);
    }

    // ---- layer3 partials + reduce ----
    const float b3v = b3[0];
    float pr[4] = {0.f, 0.f, 0.f, 0.f};
    #pragma unroll
    for (int m = 0; m < 2; m++)
        #pragma unroll
        for (int q = 0; q < 8; q++) {
            int o = wn * 64 + q * 8 + (lane & 3) * 2;
            float wa = s_w3[o], wb = s_w3[o + 1];
            pr[m * 2]     += lrelu(acc2[m][q][0] * BN_SCALE) * wa + lrelu(acc2[m][q][1] * BN_SCALE) * wb;
            pr[m * 2 + 1] += lrelu(acc2[m][q][2] * BN_SCALE) * wa + lrelu(acc2[m][q][3] * BN_SCALE) * wb;
        }
    #pragma unroll
    for (int t = 0; t < 4; t++) {
        pr[t] += __shfl_xor_sync(0xffffffffu, pr[t], 1);
        pr[t] += __shfl_xor_sync(0xffffffffu, pr[t], 2);
    }
    if ((lane & 3) == 0) {
        int g = lane >> 2;
        s_l3[wn * 128 + wm * 32 + g]      = pr[0];
        s_l3[wn * 128 + wm * 32 + g + 8]  = pr[1];
        s_l3[wn * 128 + wm * 32 + g + 16] = pr[2];
        s_l3[wn * 128 + wm * 32 + g + 24] = pr[3];
    }
    __syncthreads();
    if (tid < 128) {
        float e = s_l3[tid] + s_l3[128 + tid];
        s_erow[tid] = 1.0f / (1.0f + expf(-(e + b3v)));
    }
    __syncthreads();

    // ---- row postprocess (warp-shuffle reductions) ----
    if (tid < 128) s_erow[tid] *= s_epl[tid];
    __syncthreads();

    if (w == 0) {
        float v = s_epl[lane] + s_epl[lane + 32] + s_epl[lane + 64] + s_epl[lane + 96];
        #pragma unroll
        for (int st = 16; st > 0; st >>= 1) v += __shfl_xor_sync(0xffffffffu, v, st);
        if (lane == 0) s_red[0] = v;
    }
    int cnt = 0;
    if (kval > 0 && tid < 128) {
        float mine = s_erow[tid];
        for (int jj = 0; jj < NN; jj++) {
            float vv = s_erow[jj];
            cnt += (vv > mine) || (vv == mine && jj < tid);
        }
    }
    __syncthreads();
    if (kval > 0 && tid < 128 && cnt >= kval) s_erow[tid] = 0.f;
    __syncthreads();

    if (w == 0) {
        float v = fabsf(s_erow[lane]) + fabsf(s_erow[lane + 32])
                + fabsf(s_erow[lane + 64]) + fabsf(s_erow[lane + 96]);
        #pragma unroll
        for (int st = 16; st > 0; st >>= 1) v += __shfl_xor_sync(0xffffffffu, v, st);
        if (lane == 0) s_red[1] = v;
    }
    __syncthreads();

    const float scale = s_red[0] / fmaxf(s_red[1], 1e-12f);
    if (tid < 128)
        s_erow[tid] = s_erow[tid] * scale + ((tid == i) ? 1.0f : 0.0f) + 1e-6f;
    __syncthreads();

    if (w == 0) {
        float v = s_erow[lane] + s_erow[lane + 32] + s_erow[lane + 64] + s_erow[lane + 96];
        #pragma unroll
        for (int st = 16; st > 0; st >>= 1) v += __shfl_xor_sync(0xffffffffu, v, st);
        if (lane == 0) s_red[2] = v;
    }
    __syncthreads();

    if (tid < 128) ep_out[row * NN + tid] = s_erow[tid] / s_red[2];
}

// ---------------- Q/K projection: cp.async ring ------------------------------
__global__ void __launch_bounds__(256)
qk_kernel(const float* __restrict__ vp,
          const float* __restrict__ wq,
          const float* __restrict__ wk,
          float* __restrict__ Q,
          float* __restrict__ K)
{
    __shared__ float vr[8][CC];
    __shared__ float ring[4][2048];
    uint32_t sring;
    asm("{ .reg .u64 t; cvta.to.shared.u64 t, %1; cvt.u32.u64 %0, t; }" : "=r"(sring) : "l"(ring));
    const int rt = blockIdx.x, b = blockIdx.y;
    const int r0 = b * NN + rt * 8;
    const int tid = threadIdx.x;

    #define QK_ISSUE(ci) { \
        const float* _s = ((ci) < 8 ? wq + (ci) * 2048 : wk + ((ci) - 8) * 2048); \
        const float4* _g = (const float4*)_s + tid; \
        uint32_t _d = sring + (uint32_t)((ci) & 3) * 8192u + (uint32_t)tid * 16u; \
        CPA16(_d, (const void*)_g); \
        CPA16(_d + 4096u, (const void*)(_g + 256)); \
        CPA_COMMIT(); }

    QK_ISSUE(0); QK_ISSUE(1);

    #pragma unroll
    for (int t = 0; t < 4; t++) {
        int idx = tid + t * 256;
        vr[idx >> 7][idx & 127] = vp[r0 * CC + idx];
    }

    const int o = tid & 127, half = tid >> 7;
    float acc[8] = {0.f};

    for (int ci = 0; ci < 16; ci++) {
        if (ci + 2 < 16) { QK_ISSUE(ci + 2); CPA_WAIT2(); }
        else if (ci + 1 < 16) { CPA_WAIT1(); }
        else { CPA_WAIT0(); }
        __syncthreads();
        if ((ci < 8) == (half == 0)) {
            const float* cur = &ring[ci & 3][0];
            const int kb = (ci & 7) * 16;
            #pragma unroll
            for (int kk4 = 0; kk4 < 4; kk4++) {
                float w0 = cur[(kk4 * 4 + 0) * 128 + o];
                float w1v = cur[(kk4 * 4 + 1) * 128 + o];
                float w2v = cur[(kk4 * 4 + 2) * 128 + o];
                float w3v = cur[(kk4 * 4 + 3) * 128 + o];
                #pragma unroll
                for (int r = 0; r < 8; r++) {
                    const float4 v = *(const float4*)&vr[r][kb + kk4 * 4];
                    acc[r] += v.x * w0 + v.y * w1v + v.z * w2v + v.w * w3v;
                }
            }
        }
    }
    float* dst = half ? K : Q;
    #pragma unroll
    for (int r = 0; r < 8; r++) dst[(r0 + r) * CC + o] = acc[r];
}

// ---------------- Fused MHA + D2P: cp.async 4-buffer pipelines ---------------
#define KS_STR 132
#define FD_KS    0
#define FD_EDGE  (NN * KS_STR)
#define FD_NF    (FD_EDGE + 8 * NN)
#define FD_HB    (FD_NF + 8 * 2 * CC)
#define SMEM_FD  ((FD_HB + 8 * 2 * CC) * 4)

#define ISSUE_CH(bufidx, srcf4, chn) { \
    const float4* _g = (srcf4) + (chn) * 1024 + tid; \
    uint32_t _d = sbase + (uint32_t)(bufidx) * 16384u + (uint32_t)tid * 16u; \
    CPA16(_d, (const void*)_g); \
    CPA16(_d + 4096u, (const void*)(_g + 256)); \
    CPA16(_d + 8192u, (const void*)(_g + 512)); \
    CPA16(_d + 12288u, (const void*)(_g + 768)); \
    CPA_COMMIT(); }

__global__ void __launch_bounds__(256)
mha_d2p_kernel(const float* __restrict__ Q,
               const float* __restrict__ K,
               const float* __restrict__ ep,
               const float* __restrict__ vp,
               const float* __restrict__ w1,
               const float* __restrict__ w2,
               float* __restrict__ vp_out)
{
    extern __shared__ float fsm[];
    uint32_t sbase;
    asm("{ .reg .u64 t; cvta.to.shared.u64 t, %1; cvt.u32.u64 %0, t; }" : "=r"(sbase) : "l"(fsm));
    float* Ks = fsm + FD_KS;
    float (*edge)[NN]   = (float(*)[NN])(fsm + FD_EDGE);
    float (*nf)[2 * CC] = (float(*)[2 * CC])(fsm + FD_NF);
    float (*hb)[2 * CC] = (float(*)[2 * CC])(fsm + FD_HB);
    const int qt = blockIdx.x, b = blockIdx.y;
    const int tid = threadIdx.x, w = tid >> 5, lane = tid & 31;

    for (int idx = tid; idx < NN * 32; idx += 256) {
        int j = idx >> 5, c4 = (idx & 31) << 2;
        CPA16(sbase + (uint32_t)(j * KS_STR + c4) * 4u, (const void*)(K + (b * NN + j) * CC + c4));
    }
    CPA_COMMIT();

    const int qi = qt * 8 + w;
    const int row = b * NN + qi;
    float qreg[4];
    #pragma unroll
    for (int h = 0; h < HH; h++) qreg[h] = Q[row * CC + h * DKK + lane];
    CPA_WAIT0();
    __syncthreads();

    const float inv = 0.17677669529663687f;
    float acc[4] = {0.f, 0.f, 0.f, 0.f};
    #pragma unroll
    for (int h = 0; h < HH; h++) {
        float sc[4] = {0.f, 0.f, 0.f, 0.f};
        #pragma unroll
        for (int d4 = 0; d4 < 8; d4++) {
            float q0 = __shfl_sync(0xffffffffu, qreg[h], d4 * 4);
            float q1 = __shfl_sync(0xffffffffu, qreg[h], d4 * 4 + 1);
            float q2 = __shfl_sync(0xffffffffu, qreg[h], d4 * 4 + 2);
            float q3 = __shfl_sync(0xffffffffu, qreg[h], d4 * 4 + 3);
            #pragma unroll
            for (int kk = 0; kk < 4; kk++) {
                const float4 kv = *(const float4*)&Ks[(kk * 32 + lane) * KS_STR + h * DKK + d4 * 4];
                sc[kk] += q0 * kv.x + q1 * kv.y + q2 * kv.z + q3 * kv.w;
            }
        }
        #pragma unroll
        for (int kk = 0; kk < 4; kk++) sc[kk] *= inv;
        float mx = fmaxf(fmaxf(sc[0], sc[1]), fmaxf(sc[2], sc[3]));
        #pragma unroll
        for (int st = 16; st > 0; st >>= 1) mx = fmaxf(mx, __shfl_xor_sync(0xffffffffu, mx, st));
        float ex[4]; float sm = 0.f;
        #pragma unroll
        for (int kk = 0; kk < 4; kk++) { ex[kk] = expf(sc[kk] - mx); sm += ex[kk]; }
        #pragma unroll
        for (int st = 16; st > 0; st >>= 1) sm += __shfl_xor_sync(0xffffffffu, sm, st);
        float r = 1.0f / sm;
        #pragma unroll
        for (int kk = 0; kk < 4; kk++) acc[kk] += ex[kk] * r;
    }

    {
        float e[4];
        float ssum = 0.f;
        #pragma unroll
        for (int kk = 0; kk < 4; kk++) {
            int j = kk * 32 + lane;
            float v = ep[row * NN + j] * (acc[kk] * 0.25f);
            if (j == qi) v = 0.f;
            e[kk] = v;
            ssum += fabsf(v);
        }
        #pragma unroll
        for (int st = 16; st > 0; st >>= 1) ssum += __shfl_xor_sync(0xffffffffu, ssum, st);
        float rinv = 1.0f / fmaxf(ssum, 1e-12f);
        #pragma unroll
        for (int kk = 0; kk < 4; kk++) {
            int j = kk * 32 + lane;
            edge[w][j] = e[kk] * rinv;
            nf[w][j] = vp[row * CC + j];
        }
    }
    __syncthreads();

    const int c = tid & 127, rr = tid >> 7;

    {
        const float4* vsrc = (const float4*)(vp + b * NN * CC);
        ISSUE_CH(0, vsrc, 0);
        ISSUE_CH(1, vsrc, 1);
        float a[4] = {0.f, 0.f, 0.f, 0.f};
        for (int jc = 0; jc < 4; jc++) {
            if (jc + 2 < 4) { ISSUE_CH((jc + 2) & 3, vsrc, jc + 2); CPA_WAIT2(); }
            else if (jc + 1 < 4) { CPA_WAIT1(); }
            else { CPA_WAIT0(); }
            __syncthreads();
            const float* cur = fsm + (jc & 3) * 4096;
            #pragma unroll
            for (int jq = 0; jq < 8; jq++) {
                float v0 = cur[(jq * 4 + 0) * 128 + c];
                float v1 = cur[(jq * 4 + 1) * 128 + c];
                float v2 = cur[(jq * 4 + 2) * 128 + c];
                float v3 = cur[(jq * 4 + 3) * 128 + c];
                int j = jc * 32 + jq * 4;
                #pragma unroll
                for (int q = 0; q < 4; q++) {
                    const float4 e4 = *(const float4*)&edge[rr + 2 * q][j];
                    a[q] += e4.x * v0 + e4.y * v1 + e4.z * v2 + e4.w * v3;
                }
            }
        }
        #pragma unroll
        for (int q = 0; q < 4; q++) nf[rr + 2 * q][CC + c] = a[q];
    }

    {
        const float4* w1v = (const float4*)w1;
        ISSUE_CH(0, w1v, 0);
        ISSUE_CH(1, w1v, 1);
        float accm[8] = {0.f};
        for (int ch = 0; ch < 16; ch++) {
            if (ch + 2 < 16) { ISSUE_CH((ch + 2) & 3, w1v, ch + 2); CPA_WAIT2(); }
            else if (ch + 1 < 16) { CPA_WAIT1(); }
            else { CPA_WAIT0(); }
            __syncthreads();
            const float* cur = fsm + (ch & 3) * 4096;
            #pragma unroll
            for (int kq = 0; kq < 4; kq++) {
                float wv0 = cur[(kq * 4 + 0) * 256 + tid];
                float wv1 = cur[(kq * 4 + 1) * 256 + tid];
                float wv2 = cur[(kq * 4 + 2) * 256 + tid];
                float wv3 = cur[(kq * 4 + 3) * 256 + tid];
                int kb = ch * 16 + kq * 4;
                #pragma unroll
                for (int r = 0; r < 8; r++) {
                    const float4 aN = *(const float4*)&nf[r][kb];
                    accm[r] += aN.x * wv0 + aN.y * wv1 + aN.z * wv2 + aN.w * wv3;
                }
            }
        }
        #pragma unroll
        for (int r = 0; r < 8; r++) hb[r][tid] = lrelu(accm[r] * BN_SCALE);
    }

    {
        const float4* w2v = (const float4*)w2;
        ISSUE_CH(0, w2v, 0);
        ISSUE_CH(1, w2v, 1);
        float a[4] = {0.f, 0.f, 0.f, 0.f};
        for (int ch = 0; ch < 8; ch++) {
            if (ch + 2 < 8) { ISSUE_CH((ch + 2) & 3, w2v, ch + 2); CPA_WAIT2(); }
            else if (ch + 1 < 8) { CPA_WAIT1(); }
            else { CPA_WAIT0(); }
            __syncthreads();
            const float* cur = fsm + (ch & 3) * 4096;
            #pragma unroll
            for (int kq = 0; kq < 8; kq++) {
                float wv0 = cur[(kq * 4 + 0) * 128 + c];
                float wv1 = cur[(kq * 4 + 1) * 128 + c];
                float wv2 = cur[(kq * 4 + 2) * 128 + c];
                float wv3 = cur[(kq * 4 + 3) * 128 + c];
                int kb = ch * 32 + kq * 4;
                #pragma unroll
                for (int q = 0; q < 4; q++) {
                    const float4 h4 = *(const float4*)&hb[rr + 2 * q][kb];
                    a[q] += h4.x * wv0 + h4.y * wv1 + h4.z * wv2 + h4.w * wv3;
                }
            }
        }
        #pragma unroll
        for (int q = 0; q < 4; q++)
            vp_out[(b * NN + qt * 8 + rr + 2 * q) * CC + c] = lrelu(a[q] * BN_SCALE);
    }
}

// ---------------------------------------------------------------------------

extern "C" void kernel_launch(void* const* d_in, const int* in_sizes, int n_in,
                              void* d_out, int out_size)
{
    const float* vp   = (const float*)d_in[0];
    const float* ep0  = (const float*)d_in[1];
    const float* pw1  = (const float*)d_in[2];
    const float* pw2  = (const float*)d_in[3];
    const float* pw3  = (const float*)d_in[4];
    const float* pb3  = (const float*)d_in[5];
    const float* psw1 = (const float*)d_in[6];
    const float* psw2 = (const float*)d_in[7];
    const float* psw3 = (const float*)d_in[8];
    const float* psb3 = (const float*)d_in[9];
    const float* dw1  = (const float*)d_in[10];
    const float* dw2  = (const float*)d_in[11];
    const float* wq   = (const float*)d_in[12];
    const float* wk   = (const float*)d_in[13];
    float* out = (float*)d_out;

    cudaFuncSetAttribute(psim_mma, cudaFuncAttributeMaxDynamicSharedMemorySize, SMEM_PS);
    cudaFuncSetAttribute(mha_d2p_kernel, cudaFuncAttributeMaxDynamicSharedMemorySize, SMEM_FD);

    float *ep, *Q, *K, *vp1, *vp2;
    uint4 *w1P, *w2P;
    cudaGetSymbolAddress((void**)&ep, g_ep);
    cudaGetSymbolAddress((void**)&Q, g_Q);
    cudaGetSymbolAddress((void**)&K, g_K);
    cudaGetSymbolAddress((void**)&vp1, g_vp1);
    cudaGetSymbolAddress((void**)&vp2, g_vp2);
    cudaGetSymbolAddress((void**)&w1P, g_w1P);
    cudaGetSymbolAddress((void**)&w2P, g_w2P);

    prep_weights_all<<<dim3(16, 3), 256>>>(pw1, pw2, psw1, psw2, w1P, w2P);

    dim3 grid(NN, BB);
    dim3 grid8(16, BB);

    psim_mma<<<grid, 256, SMEM_PS>>>(vp, ep0, ep, w1P, w2P, pw3, pb3, 0);

    for (int g = 0; g < 2; g++) {
        const float* vpc = (g == 0) ? vp : vp1;
        float* vpn = (g == 0) ? vp1 : vp2;

        qk_kernel<<<grid8, 256>>>(vpc, wq + g * CC * CC, wk + g * CC * CC, Q, K);
        mha_d2p_kernel<<<grid8, 256, SMEM_FD>>>(Q, K, ep, vpc,
                                                dw1 + g * 2 * CC * 2 * CC,
                                                dw2 + g * 2 * CC * CC, vpn);

        const int kv = (g == 0) ? 115 : 102;
        float* epo = (g == 1) ? out : ep;
        psim_mma<<<grid, 256, SMEM_PS>>>(vpn, ep, epo,
                                         w1P + (g + 1) * 4096,
                                         w2P + (g + 1) * 4096,
                                         psw3 + g * CC,
                                         psb3 + g, kv);
    }
}